// round 6
// baseline (speedup 1.0000x reference)
#include <cuda_runtime.h>
#include <cuda_bf16.h>
#include <cstdint>
#include <math.h>

#define BATCH   8
#define SEQ     1024
#define DIM     768
#define HEADS   12
#define DHEAD   64
#define INNER   768
#define NQKV    2304
#define MROWS   8192
// 0.125 * log2(e): fold softmax scale and exp->exp2 conversion into Q
#define SC_LOG2E 0.1803368801111244f

// ---------------------------------------------------------------------------
// Persistent bf16 hi/lo scratch (split representation: x ~= hi + lo)
// ---------------------------------------------------------------------------
__device__ __nv_bfloat16 g_Xhi[MROWS*DIM],   g_Xlo[MROWS*DIM];
__device__ __nv_bfloat16 g_WQhi[DIM*NQKV],   g_WQlo[DIM*NQKV];
__device__ __nv_bfloat16 g_WOhi[INNER*DIM],  g_WOlo[INNER*DIM];
__device__ __nv_bfloat16 g_Qhi[BATCH*HEADS*SEQ*DHEAD], g_Qlo[BATCH*HEADS*SEQ*DHEAD];
__device__ __nv_bfloat16 g_Khi[BATCH*HEADS*SEQ*DHEAD], g_Klo[BATCH*HEADS*SEQ*DHEAD];
__device__ __nv_bfloat16 g_Vhi[BATCH*HEADS*SEQ*DHEAD], g_Vlo[BATCH*HEADS*SEQ*DHEAD];
__device__ __nv_bfloat16 g_AOhi[MROWS*INNER], g_AOlo[MROWS*INNER];

// ---------------------------------------------------------------------------
// Helpers
// ---------------------------------------------------------------------------
__device__ __forceinline__ uint32_t smem_u32(const void* p) {
    uint32_t a;
    asm("{ .reg .u64 t; cvta.to.shared.u64 t, %1; cvt.u32.u64 %0, t; }" : "=r"(a) : "l"(p));
    return a;
}
__device__ __forceinline__ void ldsm4(uint32_t addr, uint32_t* r) {
    asm volatile("ldmatrix.sync.aligned.m8n8.x4.shared.b16 {%0,%1,%2,%3}, [%4];"
                 : "=r"(r[0]), "=r"(r[1]), "=r"(r[2]), "=r"(r[3]) : "r"(addr));
}
__device__ __forceinline__ void ldsm4t(uint32_t addr, uint32_t* r) {
    asm volatile("ldmatrix.sync.aligned.m8n8.x4.trans.shared.b16 {%0,%1,%2,%3}, [%4];"
                 : "=r"(r[0]), "=r"(r[1]), "=r"(r[2]), "=r"(r[3]) : "r"(addr));
}
__device__ __forceinline__ void mma16816(float* c, const uint32_t* a, uint32_t b0, uint32_t b1) {
    asm volatile("mma.sync.aligned.m16n8k16.row.col.f32.bf16.bf16.f32 "
                 "{%0,%1,%2,%3}, {%4,%5,%6,%7}, {%8,%9}, {%0,%1,%2,%3};"
                 : "+f"(c[0]), "+f"(c[1]), "+f"(c[2]), "+f"(c[3])
                 : "r"(a[0]), "r"(a[1]), "r"(a[2]), "r"(a[3]), "r"(b0), "r"(b1));
}
__device__ __forceinline__ float fast_exp2(float x) {
    float y;
    asm("ex2.approx.f32 %0, %1;" : "=f"(y) : "f"(x));
    return y;
}
__device__ __forceinline__ void cpa16(uint32_t dst, const void* src) {
    asm volatile("cp.async.cg.shared.global [%0], [%1], 16;" :: "r"(dst), "l"(src));
}
#define CP_COMMIT() asm volatile("cp.async.commit_group;" ::: "memory")

__device__ __forceinline__ void split_pack(float x, float y,
                                           __nv_bfloat162& h2, __nv_bfloat162& l2) {
    __nv_bfloat16 hx = __float2bfloat16(x);
    __nv_bfloat16 hy = __float2bfloat16(y);
    h2 = __nv_bfloat162(hx, hy);
    l2 = __nv_bfloat162(__float2bfloat16(x - __bfloat162float(hx)),
                        __float2bfloat16(y - __bfloat162float(hy)));
}
__device__ __forceinline__ void split2_store(char* hi_p, char* lo_p, float x, float y) {
    __nv_bfloat162 h2, l2;
    split_pack(x, y, h2, l2);
    *(__nv_bfloat162*)hi_p = h2;
    *(__nv_bfloat162*)lo_p = l2;
}

// ---------------------------------------------------------------------------
// Pre-convert: fp32 -> bf16 hi/lo
// ---------------------------------------------------------------------------
template<int SEL>
__global__ void cvt_split(const float* __restrict__ src, int n)
{
    __nv_bfloat16* hi = (SEL == 0) ? g_Xhi : (SEL == 1) ? g_WQhi : g_WOhi;
    __nv_bfloat16* lo = (SEL == 0) ? g_Xlo : (SEL == 1) ? g_WQlo : g_WOlo;
    const int i = (blockIdx.x * blockDim.x + threadIdx.x) * 4;
    if (i < n) {
        float4 v = *(const float4*)(src + i);
        __nv_bfloat162 h0, l0, h1, l1;
        split_pack(v.x, v.y, h0, l0);
        split_pack(v.z, v.w, h1, l1);
        *(__nv_bfloat162*)(hi + i)     = h0;
        *(__nv_bfloat162*)(hi + i + 2) = h1;
        *(__nv_bfloat162*)(lo + i)     = l0;
        *(__nv_bfloat162*)(lo + i + 2) = l1;
    }
}

// ---------------------------------------------------------------------------
// GEMM (split-bf16 3-pass HMMA, cp.async double-buffered, pass-major MMA order)
// ---------------------------------------------------------------------------
#define G_AHI 0
#define G_ALO 18432
#define G_BHI 36864
#define G_BLO 54272
#define G_STAGE 71680
#define G_SMEM_BYTES (2*G_STAGE)

template<int MODE>
__global__ void __launch_bounds__(256, 1)
gemm_tc(const float* __restrict__ bias, float* __restrict__ out)
{
    extern __shared__ char smem[];
    const uint32_t sb = smem_u32(smem);
    const int tid  = threadIdx.x;
    const int lane = tid & 31;
    const int wid  = tid >> 5;
    const int wm   = wid & 3;
    const int wn   = wid >> 2;
    const int bx = blockIdx.x, by = blockIdx.y;

    const __nv_bfloat16* Ahi = (MODE == 0) ? g_Xhi  : g_AOhi;
    const __nv_bfloat16* Alo = (MODE == 0) ? g_Xlo  : g_AOlo;
    const __nv_bfloat16* Bhi = (MODE == 0) ? g_WQhi : g_WOhi;
    const __nv_bfloat16* Blo = (MODE == 0) ? g_WQlo : g_WOlo;
    const int ldb = (MODE == 0) ? NQKV : DIM;

    float acc[2][8][4];
    #pragma unroll
    for (int i = 0; i < 2; i++)
        #pragma unroll
        for (int j = 0; j < 8; j++)
            #pragma unroll
            for (int k = 0; k < 4; k++) acc[i][j][k] = 0.f;

    const int lrow = lane & 15;
    const int lc16 = (lane >> 4) * 16;
    const uint32_t aAhi = sb + G_AHI + (uint32_t)((wm*32 + lrow)*144) + lc16;
    const uint32_t aBhi = sb + G_BHI + (uint32_t)(lrow*272) + lc16 + (uint32_t)(wn*128);

    auto prefetch = [&](int ch, int st) {
        const int k0 = ch * 64;
        const uint32_t sa = sb + (uint32_t)st * G_STAGE;
        #pragma unroll
        for (int i = tid; i < 1024; i += 256) {
            const int row = i >> 3, seg = i & 7;
            const uint32_t d = sa + G_AHI + row*144 + seg*16;
            const size_t g = (size_t)(by*128 + row)*768 + k0 + seg*8;
            cpa16(d,                 Ahi + g);
            cpa16(d + (G_ALO-G_AHI), Alo + g);
        }
        #pragma unroll
        for (int i = tid; i < 1024; i += 256) {
            const int row = i >> 4, seg = i & 15;
            const uint32_t d = sa + G_BHI + row*272 + seg*16;
            const size_t g = (size_t)(k0 + row)*ldb + bx*128 + seg*8;
            cpa16(d,                 Bhi + g);
            cpa16(d + (G_BLO-G_BHI), Blo + g);
        }
    };

    prefetch(0, 0);
    CP_COMMIT();

    for (int ch = 0; ch < 12; ch++) {
        if (ch + 1 < 12) { prefetch(ch + 1, (ch + 1) & 1); CP_COMMIT(); }
        if (ch + 1 < 12) { asm volatile("cp.async.wait_group 1;" ::: "memory"); }
        else             { asm volatile("cp.async.wait_group 0;" ::: "memory"); }
        __syncthreads();

        const uint32_t so = (uint32_t)(ch & 1) * G_STAGE;
        #pragma unroll
        for (int ks = 0; ks < 4; ks++) {
            // Load ALL fragments for this ks first
            uint32_t ah[2][4], al[2][4];
            ldsm4(aAhi + so + ks*32,                          ah[0]);
            ldsm4(aAhi + so + 16*144 + ks*32,                 ah[1]);
            ldsm4(aAhi + so + (G_ALO-G_AHI) + ks*32,          al[0]);
            ldsm4(aAhi + so + (G_ALO-G_AHI) + 16*144 + ks*32, al[1]);
            uint32_t bh[4][4], bl[4][4];
            #pragma unroll
            for (int np = 0; np < 4; np++) {
                ldsm4t(aBhi + so + ks*4352 + np*32,                 bh[np]);
                ldsm4t(aBhi + so + (G_BLO-G_BHI) + ks*4352 + np*32, bl[np]);
            }
            // Pass-major issue order: 16 independent MMAs between reuses of an acc
            #pragma unroll
            for (int np = 0; np < 4; np++)      // hh
                #pragma unroll
                for (int mt = 0; mt < 2; mt++) {
                    mma16816(acc[mt][np*2+0], ah[mt], bh[np][0], bh[np][1]);
                    mma16816(acc[mt][np*2+1], ah[mt], bh[np][2], bh[np][3]);
                }
            #pragma unroll
            for (int np = 0; np < 4; np++)      // hl
                #pragma unroll
                for (int mt = 0; mt < 2; mt++) {
                    mma16816(acc[mt][np*2+0], ah[mt], bl[np][0], bl[np][1]);
                    mma16816(acc[mt][np*2+1], ah[mt], bl[np][2], bl[np][3]);
                }
            #pragma unroll
            for (int np = 0; np < 4; np++)      // lh
                #pragma unroll
                for (int mt = 0; mt < 2; mt++) {
                    mma16816(acc[mt][np*2+0], al[mt], bh[np][0], bh[np][1]);
                    mma16816(acc[mt][np*2+1], al[mt], bh[np][2], bh[np][3]);
                }
        }
        __syncthreads();
    }

    // Epilogue
    #pragma unroll
    for (int mt = 0; mt < 2; mt++) {
        const int row0 = by*128 + wm*32 + mt*16 + (lane >> 2);
        #pragma unroll
        for (int nt = 0; nt < 8; nt++) {
            const int col = bx*128 + wn*64 + nt*8 + (lane & 3)*2;
            if (MODE == 0) {
                const int sel = col / INNER;
                __nv_bfloat16* dhi = (sel == 0) ? g_Qhi : (sel == 1) ? g_Khi : g_Vhi;
                __nv_bfloat16* dlo = (sel == 0) ? g_Qlo : (sel == 1) ? g_Klo : g_Vlo;
                const float sc = (sel == 0) ? SC_LOG2E : 1.f;
                const int cr = col - sel*INNER;
                const int h = cr >> 6, d = cr & 63;
                {
                    const int b = row0 >> 10, nn = row0 & 1023;
                    const size_t idx = (size_t)(((b*HEADS + h) << 10) + nn)*DHEAD + d;
                    __nv_bfloat162 h2, l2;
                    split_pack(acc[mt][nt][0]*sc, acc[mt][nt][1]*sc, h2, l2);
                    *(__nv_bfloat162*)(dhi + idx) = h2;
                    *(__nv_bfloat162*)(dlo + idx) = l2;
                }
                {
                    const int r1 = row0 + 8;
                    const int b = r1 >> 10, nn = r1 & 1023;
                    const size_t idx = (size_t)(((b*HEADS + h) << 10) + nn)*DHEAD + d;
                    __nv_bfloat162 h2, l2;
                    split_pack(acc[mt][nt][2]*sc, acc[mt][nt][3]*sc, h2, l2);
                    *(__nv_bfloat162*)(dhi + idx) = h2;
                    *(__nv_bfloat162*)(dlo + idx) = l2;
                }
            } else {
                const float b0 = bias[col], b1 = bias[col+1];
                *(float2*)&out[(size_t)row0*DIM + col] =
                    make_float2(acc[mt][nt][0] + b0, acc[mt][nt][1] + b1);
                *(float2*)&out[(size_t)(row0+8)*DIM + col] =
                    make_float2(acc[mt][nt][2] + b0, acc[mt][nt][3] + b1);
            }
        }
    }
}

// ---------------------------------------------------------------------------
// Attention (HMMA, unnormalized log2-domain softmax, pass-major MMA order)
// ---------------------------------------------------------------------------
#define A_QHI 0
#define A_QLO 18432
#define A_KV0 36864
#define A_KHIo 0
#define A_KLOo 9216
#define A_VHIo 18432
#define A_VLOo 27648
#define A_STAGE 36864
#define A_PHI 110592
#define A_PLO 129024
#define A_RSP 147456
#define A_RSA 148480
#define A_SMEM_BYTES 148992

__global__ void __launch_bounds__(256, 1)
attn_tc()
{
    extern __shared__ char smem[];
    const uint32_t sb = smem_u32(smem);
    const int tid  = threadIdx.x;
    const int lane = tid & 31;
    const int wid  = tid >> 5;
    const int wm   = wid & 3;
    const int wn   = wid >> 2;
    const int bh = blockIdx.y;
    const int q0 = blockIdx.x * 128;

    float* rsp = (float*)(smem + A_RSP);
    float* rsa = (float*)(smem + A_RSA);
    if (tid < 128) rsa[tid] = 0.f;

    const size_t qbase = ((size_t)bh*SEQ + q0) * DHEAD;

    auto prefetchKV = [&](int c, int st) {
        const size_t g0 = ((size_t)bh*SEQ + c*64) * DHEAD;
        const uint32_t sa = sb + A_KV0 + (uint32_t)st * A_STAGE;
        #pragma unroll
        for (int i = tid; i < 512; i += 256) {
            const int row = i >> 3, seg = i & 7;
            const uint32_t d = sa + row*144 + seg*16;
            const size_t g = g0 + row*64 + seg*8;
            cpa16(d + A_KHIo, g_Khi + g);
            cpa16(d + A_KLOo, g_Klo + g);
            cpa16(d + A_VHIo, g_Vhi + g);
            cpa16(d + A_VLOo, g_Vlo + g);
        }
    };

    #pragma unroll
    for (int i = tid; i < 1024; i += 256) {
        const int row = i >> 3, seg = i & 7;
        const uint32_t d = sb + A_QHI + row*144 + seg*16;
        const size_t g = qbase + row*64 + seg*8;
        cpa16(d,                 g_Qhi + g);
        cpa16(d + (A_QLO-A_QHI), g_Qlo + g);
    }
    prefetchKV(0, 0);
    CP_COMMIT();

    float o[2][4][4];
    #pragma unroll
    for (int i = 0; i < 2; i++)
        #pragma unroll
        for (int j = 0; j < 4; j++)
            #pragma unroll
            for (int k = 0; k < 4; k++) o[i][j][k] = 0.f;

    const int lrow = lane & 15;
    const int lc16 = (lane >> 4) * 16;
    const uint32_t aQhi = sb + A_QHI + (uint32_t)((wm*32 + lrow)*144) + lc16;
    const uint32_t aKhi = sb + A_KV0 + A_KHIo + (uint32_t)((wn*32 + lrow)*144) + lc16;
    const uint32_t aVhi = sb + A_KV0 + A_VHIo + (uint32_t)(lrow*144) + lc16 + (uint32_t)(wn*64);
    const uint32_t aPhi = sb + A_PHI + (uint32_t)((wm*32 + lrow)*144) + lc16;

    for (int c = 0; c < 16; c++) {
        if (c + 1 < 16) { prefetchKV(c + 1, (c + 1) & 1); CP_COMMIT(); }
        if (c + 1 < 16) { asm volatile("cp.async.wait_group 1;" ::: "memory"); }
        else            { asm volatile("cp.async.wait_group 0;" ::: "memory"); }
        __syncthreads();

        const uint32_t so = (uint32_t)(c & 1) * A_STAGE;

        // ---- S = Q @ K^T ----
        float s[2][4][4];
        #pragma unroll
        for (int i = 0; i < 2; i++)
            #pragma unroll
            for (int j = 0; j < 4; j++)
                #pragma unroll
                for (int k = 0; k < 4; k++) s[i][j][k] = 0.f;

        #pragma unroll
        for (int ks = 0; ks < 4; ks++) {
            uint32_t qh[2][4], ql[2][4];
            ldsm4(aQhi + ks*32,                          qh[0]);
            ldsm4(aQhi + 16*144 + ks*32,                 qh[1]);
            ldsm4(aQhi + (A_QLO-A_QHI) + ks*32,          ql[0]);
            ldsm4(aQhi + (A_QLO-A_QHI) + 16*144 + ks*32, ql[1]);
            uint32_t kh[2][4], kl[2][4];
            #pragma unroll
            for (int np = 0; np < 2; np++) {
                ldsm4(aKhi + so + np*16*144 + ks*32,                 kh[np]);
                ldsm4(aKhi + so + (A_KLOo-A_KHIo) + np*16*144 + ks*32, kl[np]);
            }
            // pass-major (non-trans pairing: {r0,r2} / {r1,r3})
            #pragma unroll
            for (int np = 0; np < 2; np++)
                #pragma unroll
                for (int mt = 0; mt < 2; mt++) {
                    mma16816(s[mt][np*2+0], qh[mt], kh[np][0], kh[np][2]);
                    mma16816(s[mt][np*2+1], qh[mt], kh[np][1], kh[np][3]);
                }
            #pragma unroll
            for (int np = 0; np < 2; np++)
                #pragma unroll
                for (int mt = 0; mt < 2; mt++) {
                    mma16816(s[mt][np*2+0], qh[mt], kl[np][0], kl[np][2]);
                    mma16816(s[mt][np*2+1], qh[mt], kl[np][1], kl[np][3]);
                }
            #pragma unroll
            for (int np = 0; np < 2; np++)
                #pragma unroll
                for (int mt = 0; mt < 2; mt++) {
                    mma16816(s[mt][np*2+0], ql[mt], kh[np][0], kh[np][2]);
                    mma16816(s[mt][np*2+1], ql[mt], kh[np][1], kh[np][3]);
                }
        }

        // ---- P = 2^S, row sums, P -> smem ----
        #pragma unroll
        for (int mt = 0; mt < 2; mt++) {
            float rs0 = 0.f, rs1 = 0.f;
            const int prow = wm*32 + mt*16 + (lane >> 2);
            #pragma unroll
            for (int nt = 0; nt < 4; nt++) {
                const float e0 = fast_exp2(s[mt][nt][0]);
                const float e1 = fast_exp2(s[mt][nt][1]);
                const float e2 = fast_exp2(s[mt][nt][2]);
                const float e3 = fast_exp2(s[mt][nt][3]);
                rs0 += e0 + e1;
                rs1 += e2 + e3;
                const int pcol = wn*32 + nt*8 + (lane & 3)*2;
                const uint32_t off0 = (uint32_t)(prow*144 + pcol*2);
                split2_store(smem + A_PHI + off0, smem + A_PLO + off0, e0, e1);
                const uint32_t off1 = off0 + 8*144;
                split2_store(smem + A_PHI + off1, smem + A_PLO + off1, e2, e3);
            }
            rs0 += __shfl_xor_sync(0xffffffffu, rs0, 1);
            rs0 += __shfl_xor_sync(0xffffffffu, rs0, 2);
            rs1 += __shfl_xor_sync(0xffffffffu, rs1, 1);
            rs1 += __shfl_xor_sync(0xffffffffu, rs1, 2);
            if ((lane & 3) == 0) {
                rsp[wn*128 + prow]     = rs0;
                rsp[wn*128 + prow + 8] = rs1;
            }
        }
        __syncthreads();
        if (tid < 128) rsa[tid] += rsp[tid] + rsp[128 + tid];

        // ---- O += P @ V ----
        #pragma unroll
        for (int ks = 0; ks < 4; ks++) {
            uint32_t ph[2][4], pl[2][4];
            ldsm4(aPhi + ks*32,                          ph[0]);
            ldsm4(aPhi + 16*144 + ks*32,                 ph[1]);
            ldsm4(aPhi + (A_PLO-A_PHI) + ks*32,          pl[0]);
            ldsm4(aPhi + (A_PLO-A_PHI) + 16*144 + ks*32, pl[1]);
            uint32_t vh[2][4], vl[2][4];
            #pragma unroll
            for (int np = 0; np < 2; np++) {
                ldsm4t(aVhi + so + ks*16*144 + np*32,                   vh[np]);
                ldsm4t(aVhi + so + (A_VLOo-A_VHIo) + ks*16*144 + np*32, vl[np]);
            }
            // pass-major (trans pairing: {r0,r1} / {r2,r3})
            #pragma unroll
            for (int np = 0; np < 2; np++)
                #pragma unroll
                for (int mt = 0; mt < 2; mt++) {
                    mma16816(o[mt][np*2+0], ph[mt], vh[np][0], vh[np][1]);
                    mma16816(o[mt][np*2+1], ph[mt], vh[np][2], vh[np][3]);
                }
            #pragma unroll
            for (int np = 0; np < 2; np++)
                #pragma unroll
                for (int mt = 0; mt < 2; mt++) {
                    mma16816(o[mt][np*2+0], ph[mt], vl[np][0], vl[np][1]);
                    mma16816(o[mt][np*2+1], ph[mt], vl[np][2], vl[np][3]);
                }
            #pragma unroll
            for (int np = 0; np < 2; np++)
                #pragma unroll
                for (int mt = 0; mt < 2; mt++) {
                    mma16816(o[mt][np*2+0], pl[mt], vh[np][0], vh[np][1]);
                    mma16816(o[mt][np*2+1], pl[mt], vh[np][2], vh[np][3]);
                }
        }
        __syncthreads();
    }

    // Normalize + split-store AO
    const int b = bh / HEADS;
    const int h = bh - b*HEADS;
    #pragma unroll
    for (int mt = 0; mt < 2; mt++) {
        const int row0 = wm*32 + mt*16 + (lane >> 2);
        const float inv0 = 1.f / rsa[row0];
        const float inv1 = 1.f / rsa[row0 + 8];
        #pragma unroll
        for (int nt = 0; nt < 4; nt++) {
            const int d = wn*32 + nt*8 + (lane & 3)*2;
            {
                const size_t idx = (size_t)(b*SEQ + q0 + row0)*INNER + h*DHEAD + d;
                __nv_bfloat162 h2, l2;
                split_pack(o[mt][nt][0]*inv0, o[mt][nt][1]*inv0, h2, l2);
                *(__nv_bfloat162*)(g_AOhi + idx) = h2;
                *(__nv_bfloat162*)(g_AOlo + idx) = l2;
            }
            {
                const size_t idx = (size_t)(b*SEQ + q0 + row0 + 8)*INNER + h*DHEAD + d;
                __nv_bfloat162 h2, l2;
                split_pack(o[mt][nt][2]*inv1, o[mt][nt][3]*inv1, h2, l2);
                *(__nv_bfloat162*)(g_AOhi + idx) = h2;
                *(__nv_bfloat162*)(g_AOlo + idx) = l2;
            }
        }
    }
}

// ---------------------------------------------------------------------------
// Launch
// ---------------------------------------------------------------------------
extern "C" void kernel_launch(void* const* d_in, const int* in_sizes, int n_in,
                              void* d_out, int out_size)
{
    const float* x     = (const float*)d_in[0];
    const float* w_qkv = (const float*)d_in[1];
    const float* w_out = (const float*)d_in[2];
    const float* b_out = (const float*)d_in[3];
    float* out = (float*)d_out;

    cudaFuncSetAttribute(gemm_tc<0>, cudaFuncAttributeMaxDynamicSharedMemorySize, G_SMEM_BYTES);
    cudaFuncSetAttribute(gemm_tc<1>, cudaFuncAttributeMaxDynamicSharedMemorySize, G_SMEM_BYTES);
    cudaFuncSetAttribute(attn_tc,    cudaFuncAttributeMaxDynamicSharedMemorySize, A_SMEM_BYTES);

    cvt_split<0><<<(MROWS*DIM)/1024, 256>>>(x, MROWS*DIM);
    cvt_split<1><<<(DIM*NQKV)/1024, 256>>>(w_qkv, DIM*NQKV);
    cvt_split<2><<<(INNER*DIM)/1024, 256>>>(w_out, INNER*DIM);

    dim3 g1(NQKV/128, MROWS/128);   // 18 x 64
    gemm_tc<0><<<g1, 256, G_SMEM_BYTES>>>(nullptr, nullptr);

    dim3 g2(SEQ/128, BATCH*HEADS);  // 8 x 96
    attn_tc<<<g2, 256, A_SMEM_BYTES>>>();

    dim3 g3(DIM/128, MROWS/128);    // 6 x 64
    gemm_tc<1><<<g3, 256, G_SMEM_BYTES>>>(b_out, out);
}

// round 8
// speedup vs baseline: 1.1168x; 1.1168x over previous
#include <cuda_runtime.h>
#include <cuda_bf16.h>
#include <cstdint>
#include <math.h>

#define BATCH   8
#define SEQ     1024
#define DIM     768
#define HEADS   12
#define DHEAD   64
#define INNER   768
#define NQKV    2304
#define MROWS   8192
#define SC_LOG2E 0.1803368801111244f

// ---------------------------------------------------------------------------
// Persistent bf16 hi/lo scratch (x ~= hi + lo)
// ---------------------------------------------------------------------------
__device__ __nv_bfloat16 g_Xhi[MROWS*DIM],   g_Xlo[MROWS*DIM];
__device__ __nv_bfloat16 g_WQhi[DIM*NQKV],   g_WQlo[DIM*NQKV];
__device__ __nv_bfloat16 g_WOhi[INNER*DIM],  g_WOlo[INNER*DIM];
__device__ __nv_bfloat16 g_Qhi[BATCH*HEADS*SEQ*DHEAD], g_Qlo[BATCH*HEADS*SEQ*DHEAD];
__device__ __nv_bfloat16 g_Khi[BATCH*HEADS*SEQ*DHEAD], g_Klo[BATCH*HEADS*SEQ*DHEAD];
__device__ __nv_bfloat16 g_Vhi[BATCH*HEADS*SEQ*DHEAD], g_Vlo[BATCH*HEADS*SEQ*DHEAD];
__device__ __nv_bfloat16 g_AOhi[MROWS*INNER], g_AOlo[MROWS*INNER];

// ---------------------------------------------------------------------------
// Helpers
// ---------------------------------------------------------------------------
__device__ __forceinline__ uint32_t smem_u32(const void* p) {
    uint32_t a;
    asm("{ .reg .u64 t; cvta.to.shared.u64 t, %1; cvt.u32.u64 %0, t; }" : "=r"(a) : "l"(p));
    return a;
}
__device__ __forceinline__ void ldsm4(uint32_t addr, uint32_t* r) {
    asm volatile("ldmatrix.sync.aligned.m8n8.x4.shared.b16 {%0,%1,%2,%3}, [%4];"
                 : "=r"(r[0]), "=r"(r[1]), "=r"(r[2]), "=r"(r[3]) : "r"(addr));
}
__device__ __forceinline__ void ldsm4t(uint32_t addr, uint32_t* r) {
    asm volatile("ldmatrix.sync.aligned.m8n8.x4.trans.shared.b16 {%0,%1,%2,%3}, [%4];"
                 : "=r"(r[0]), "=r"(r[1]), "=r"(r[2]), "=r"(r[3]) : "r"(addr));
}
__device__ __forceinline__ void mma16816(float* c, const uint32_t* a, uint32_t b0, uint32_t b1) {
    asm volatile("mma.sync.aligned.m16n8k16.row.col.f32.bf16.bf16.f32 "
                 "{%0,%1,%2,%3}, {%4,%5,%6,%7}, {%8,%9}, {%0,%1,%2,%3};"
                 : "+f"(c[0]), "+f"(c[1]), "+f"(c[2]), "+f"(c[3])
                 : "r"(a[0]), "r"(a[1]), "r"(a[2]), "r"(a[3]), "r"(b0), "r"(b1));
}
__device__ __forceinline__ float fast_exp2(float x) {
    float y;
    asm("ex2.approx.f32 %0, %1;" : "=f"(y) : "f"(x));
    return y;
}
__device__ __forceinline__ void cpa16(uint32_t dst, const void* src) {
    asm volatile("cp.async.cg.shared.global [%0], [%1], 16;" :: "r"(dst), "l"(src));
}
#define CP_COMMIT() asm volatile("cp.async.commit_group;" ::: "memory")

__device__ __forceinline__ void split_pack(float x, float y,
                                           __nv_bfloat162& h2, __nv_bfloat162& l2) {
    __nv_bfloat16 hx = __float2bfloat16(x);
    __nv_bfloat16 hy = __float2bfloat16(y);
    h2 = __nv_bfloat162(hx, hy);
    l2 = __nv_bfloat162(__float2bfloat16(x - __bfloat162float(hx)),
                        __float2bfloat16(y - __bfloat162float(hy)));
}
__device__ __forceinline__ void split2_store(char* hi_p, char* lo_p, float x, float y) {
    __nv_bfloat162 h2, l2;
    split_pack(x, y, h2, l2);
    *(__nv_bfloat162*)hi_p = h2;
    *(__nv_bfloat162*)lo_p = l2;
}

// ---------------------------------------------------------------------------
// Pre-convert: fp32 -> bf16 hi/lo
// ---------------------------------------------------------------------------
template<int SEL>
__global__ void cvt_split(const float* __restrict__ src, int n)
{
    __nv_bfloat16* hi = (SEL == 0) ? g_Xhi : (SEL == 1) ? g_WQhi : g_WOhi;
    __nv_bfloat16* lo = (SEL == 0) ? g_Xlo : (SEL == 1) ? g_WQlo : g_WOlo;
    const int i = (blockIdx.x * blockDim.x + threadIdx.x) * 4;
    if (i < n) {
        float4 v = *(const float4*)(src + i);
        __nv_bfloat162 h0, l0, h1, l1;
        split_pack(v.x, v.y, h0, l0);
        split_pack(v.z, v.w, h1, l1);
        *(__nv_bfloat162*)(hi + i)     = h0;
        *(__nv_bfloat162*)(hi + i + 2) = h1;
        *(__nv_bfloat162*)(lo + i)     = l0;
        *(__nv_bfloat162*)(lo + i + 2) = l1;
    }
}

// ---------------------------------------------------------------------------
// GEMM (split-bf16 3-pass HMMA, K-chunk 32, double-buffered, 2 CTAs/SM)
// A stage: [128 rows][80 B] hi+lo.  B stage: [32 k][272 B] hi+lo.
// ---------------------------------------------------------------------------
#define G_AHI 0
#define G_ALO 10240
#define G_BHI 20480
#define G_BLO 29184
#define G_STAGE 37888
#define G_SMEM_BYTES (2*G_STAGE)

template<int MODE>
__global__ void __launch_bounds__(256, 2)
gemm_tc(const float* __restrict__ bias, float* __restrict__ out)
{
    extern __shared__ char smem[];
    const uint32_t sb = smem_u32(smem);
    const int tid  = threadIdx.x;
    const int lane = tid & 31;
    const int wid  = tid >> 5;
    const int wm   = wid & 3;
    const int wn   = wid >> 2;
    const int bx = blockIdx.x, by = blockIdx.y;

    const __nv_bfloat16* Ahi = (MODE == 0) ? g_Xhi  : g_AOhi;
    const __nv_bfloat16* Alo = (MODE == 0) ? g_Xlo  : g_AOlo;
    const __nv_bfloat16* Bhi = (MODE == 0) ? g_WQhi : g_WOhi;
    const __nv_bfloat16* Blo = (MODE == 0) ? g_WQlo : g_WOlo;
    const int ldb = (MODE == 0) ? NQKV : DIM;

    float acc[2][8][4];
    #pragma unroll
    for (int i = 0; i < 2; i++)
        #pragma unroll
        for (int j = 0; j < 8; j++)
            #pragma unroll
            for (int k = 0; k < 4; k++) acc[i][j][k] = 0.f;

    const int lrow = lane & 15;
    const int lc16 = (lane >> 4) * 16;
    const uint32_t aAhi = sb + G_AHI + (uint32_t)((wm*32 + lrow)*80) + lc16;
    const uint32_t aBhi = sb + G_BHI + (uint32_t)(lrow*272) + lc16 + (uint32_t)(wn*128);

    auto prefetch = [&](int ch, int st) {
        const int k0 = ch * 32;
        const uint32_t sa = sb + (uint32_t)st * G_STAGE;
        #pragma unroll
        for (int i = tid; i < 512; i += 256) {
            const int row = i >> 2, seg = i & 3;
            const uint32_t d = sa + G_AHI + row*80 + seg*16;
            const size_t g = (size_t)(by*128 + row)*768 + k0 + seg*8;
            cpa16(d,                 Ahi + g);
            cpa16(d + (G_ALO-G_AHI), Alo + g);
        }
        #pragma unroll
        for (int i = tid; i < 512; i += 256) {
            const int row = i >> 4, seg = i & 15;
            const uint32_t d = sa + G_BHI + row*272 + seg*16;
            const size_t g = (size_t)(k0 + row)*ldb + bx*128 + seg*8;
            cpa16(d,                 Bhi + g);
            cpa16(d + (G_BLO-G_BHI), Blo + g);
        }
    };

    prefetch(0, 0);
    CP_COMMIT();

    for (int ch = 0; ch < 24; ch++) {
        if (ch + 1 < 24) { prefetch(ch + 1, (ch + 1) & 1); CP_COMMIT(); }
        if (ch + 1 < 24) { asm volatile("cp.async.wait_group 1;" ::: "memory"); }
        else             { asm volatile("cp.async.wait_group 0;" ::: "memory"); }
        __syncthreads();

        const uint32_t so = (uint32_t)(ch & 1) * G_STAGE;
        #pragma unroll
        for (int ks = 0; ks < 2; ks++) {
            uint32_t ah[2][4], al[2][4];
            ldsm4(aAhi + so + ks*32,                         ah[0]);
            ldsm4(aAhi + so + 16*80 + ks*32,                 ah[1]);
            ldsm4(aAhi + so + (G_ALO-G_AHI) + ks*32,         al[0]);
            ldsm4(aAhi + so + (G_ALO-G_AHI) + 16*80 + ks*32, al[1]);
            uint32_t bh[4][4];
            #pragma unroll
            for (int np = 0; np < 4; np++)
                ldsm4t(aBhi + so + ks*4352 + np*32, bh[np]);
            // hh pass
            #pragma unroll
            for (int np = 0; np < 4; np++)
                #pragma unroll
                for (int mt = 0; mt < 2; mt++) {
                    mma16816(acc[mt][np*2+0], ah[mt], bh[np][0], bh[np][1]);
                    mma16816(acc[mt][np*2+1], ah[mt], bh[np][2], bh[np][3]);
                }
            // lh pass (uses bh; al dies after)
            #pragma unroll
            for (int np = 0; np < 4; np++)
                #pragma unroll
                for (int mt = 0; mt < 2; mt++) {
                    mma16816(acc[mt][np*2+0], al[mt], bh[np][0], bh[np][1]);
                    mma16816(acc[mt][np*2+1], al[mt], bh[np][2], bh[np][3]);
                }
            // hl pass (bl loaded after bh no longer needed)
            uint32_t bl[4][4];
            #pragma unroll
            for (int np = 0; np < 4; np++)
                ldsm4t(aBhi + so + (G_BLO-G_BHI) + ks*4352 + np*32, bl[np]);
            #pragma unroll
            for (int np = 0; np < 4; np++)
                #pragma unroll
                for (int mt = 0; mt < 2; mt++) {
                    mma16816(acc[mt][np*2+0], ah[mt], bl[np][0], bl[np][1]);
                    mma16816(acc[mt][np*2+1], ah[mt], bl[np][2], bl[np][3]);
                }
        }
        __syncthreads();
    }

    // Epilogue
    #pragma unroll
    for (int mt = 0; mt < 2; mt++) {
        const int row0 = by*128 + wm*32 + mt*16 + (lane >> 2);
        #pragma unroll
        for (int nt = 0; nt < 8; nt++) {
            const int col = bx*128 + wn*64 + nt*8 + (lane & 3)*2;
            if (MODE == 0) {
                const int sel = col / INNER;
                __nv_bfloat16* dhi = (sel == 0) ? g_Qhi : (sel == 1) ? g_Khi : g_Vhi;
                __nv_bfloat16* dlo = (sel == 0) ? g_Qlo : (sel == 1) ? g_Klo : g_Vlo;
                const float sc = (sel == 0) ? SC_LOG2E : 1.f;
                const int cr = col - sel*INNER;
                const int h = cr >> 6, d = cr & 63;
                {
                    const int b = row0 >> 10, nn = row0 & 1023;
                    const size_t idx = (size_t)(((b*HEADS + h) << 10) + nn)*DHEAD + d;
                    __nv_bfloat162 h2, l2;
                    split_pack(acc[mt][nt][0]*sc, acc[mt][nt][1]*sc, h2, l2);
                    *(__nv_bfloat162*)(dhi + idx) = h2;
                    *(__nv_bfloat162*)(dlo + idx) = l2;
                }
                {
                    const int r1 = row0 + 8;
                    const int b = r1 >> 10, nn = r1 & 1023;
                    const size_t idx = (size_t)(((b*HEADS + h) << 10) + nn)*DHEAD + d;
                    __nv_bfloat162 h2, l2;
                    split_pack(acc[mt][nt][2]*sc, acc[mt][nt][3]*sc, h2, l2);
                    *(__nv_bfloat162*)(dhi + idx) = h2;
                    *(__nv_bfloat162*)(dlo + idx) = l2;
                }
            } else {
                const float b0 = bias[col], b1 = bias[col+1];
                *(float2*)&out[(size_t)row0*DIM + col] =
                    make_float2(acc[mt][nt][0] + b0, acc[mt][nt][1] + b1);
                *(float2*)&out[(size_t)(row0+8)*DIM + col] =
                    make_float2(acc[mt][nt][2] + b0, acc[mt][nt][3] + b1);
            }
        }
    }
}

// ---------------------------------------------------------------------------
// Attention: single-buffered K/V with split prefetch (K after S, V after PV),
// 2 CTAs/SM. 128 queries/CTA, 16 chunks of 64 keys, 8 warps (4m x 2n).
// ---------------------------------------------------------------------------
#define A_QHI 0
#define A_QLO 18432
#define A_KHI 36864
#define A_KLO 46080
#define A_VHI 55296
#define A_VLO 64512
#define A_PHI 73728
#define A_PLO 92160
#define A_RSP 110592
#define A_RSA 111616
#define A_SMEM_BYTES 112128

__global__ void __launch_bounds__(256, 2)
attn_tc()
{
    extern __shared__ char smem[];
    const uint32_t sb = smem_u32(smem);
    const int tid  = threadIdx.x;
    const int lane = tid & 31;
    const int wid  = tid >> 5;
    const int wm   = wid & 3;
    const int wn   = wid >> 2;
    const int bh = blockIdx.y;
    const int q0 = blockIdx.x * 128;

    float* rsp = (float*)(smem + A_RSP);
    float* rsa = (float*)(smem + A_RSA);
    if (tid < 128) rsa[tid] = 0.f;

    const size_t base = (size_t)bh * SEQ * DHEAD;

    auto prefetchK = [&](int c) {
        const size_t g0 = base + (size_t)c*64*DHEAD;
        #pragma unroll
        for (int i = tid; i < 512; i += 256) {
            const int row = i >> 3, seg = i & 7;
            const uint32_t d = sb + A_KHI + row*144 + seg*16;
            const size_t g = g0 + row*64 + seg*8;
            cpa16(d,                 g_Khi + g);
            cpa16(d + (A_KLO-A_KHI), g_Klo + g);
        }
    };
    auto prefetchV = [&](int c) {
        const size_t g0 = base + (size_t)c*64*DHEAD;
        #pragma unroll
        for (int i = tid; i < 512; i += 256) {
            const int row = i >> 3, seg = i & 7;
            const uint32_t d = sb + A_VHI + row*144 + seg*16;
            const size_t g = g0 + row*64 + seg*8;
            cpa16(d,                 g_Vhi + g);
            cpa16(d + (A_VLO-A_VHI), g_Vlo + g);
        }
    };

    // Q + first K/V (Q address includes the (b,h) base — R7's bug was here)
    #pragma unroll
    for (int i = tid; i < 1024; i += 256) {
        const int row = i >> 3, seg = i & 7;
        const uint32_t d = sb + A_QHI + row*144 + seg*16;
        const size_t g = base + (size_t)(q0 + row)*DHEAD + seg*8;
        cpa16(d,                 g_Qhi + g);
        cpa16(d + (A_QLO-A_QHI), g_Qlo + g);
    }
    prefetchK(0);
    prefetchV(0);
    CP_COMMIT();

    float o[2][4][4];
    #pragma unroll
    for (int i = 0; i < 2; i++)
        #pragma unroll
        for (int j = 0; j < 4; j++)
            #pragma unroll
            for (int k = 0; k < 4; k++) o[i][j][k] = 0.f;

    const int lrow = lane & 15;
    const int lc16 = (lane >> 4) * 16;
    const uint32_t aQhi = sb + A_QHI + (uint32_t)((wm*32 + lrow)*144) + lc16;
    const uint32_t aKhi = sb + A_KHI + (uint32_t)((wn*32 + lrow)*144) + lc16;
    const uint32_t aVhi = sb + A_VHI + (uint32_t)(lrow*144) + lc16 + (uint32_t)(wn*64);
    const uint32_t aPhi = sb + A_PHI + (uint32_t)((wm*32 + lrow)*144) + lc16;

    for (int c = 0; c < 16; c++) {
        asm volatile("cp.async.wait_group 0;" ::: "memory");
        __syncthreads();

        // ---- S = Q @ K^T (3-pass) ----
        float s[2][4][4];
        #pragma unroll
        for (int i = 0; i < 2; i++)
            #pragma unroll
            for (int j = 0; j < 4; j++)
                #pragma unroll
                for (int k = 0; k < 4; k++) s[i][j][k] = 0.f;

        #pragma unroll
        for (int ks = 0; ks < 4; ks++) {
            uint32_t qh[2][4], ql[2][4];
            ldsm4(aQhi + ks*32,                          qh[0]);
            ldsm4(aQhi + 16*144 + ks*32,                 qh[1]);
            ldsm4(aQhi + (A_QLO-A_QHI) + ks*32,          ql[0]);
            ldsm4(aQhi + (A_QLO-A_QHI) + 16*144 + ks*32, ql[1]);
            uint32_t kh[2][4], kl[2][4];
            #pragma unroll
            for (int np = 0; np < 2; np++) {
                ldsm4(aKhi + np*16*144 + ks*32,                 kh[np]);
                ldsm4(aKhi + (A_KLO-A_KHI) + np*16*144 + ks*32, kl[np]);
            }
            #pragma unroll
            for (int np = 0; np < 2; np++)
                #pragma unroll
                for (int mt = 0; mt < 2; mt++) {
                    mma16816(s[mt][np*2+0], qh[mt], kh[np][0], kh[np][2]);
                    mma16816(s[mt][np*2+1], qh[mt], kh[np][1], kh[np][3]);
                }
            #pragma unroll
            for (int np = 0; np < 2; np++)
                #pragma unroll
                for (int mt = 0; mt < 2; mt++) {
                    mma16816(s[mt][np*2+0], ql[mt], kh[np][0], kh[np][2]);
                    mma16816(s[mt][np*2+1], ql[mt], kh[np][1], kh[np][3]);
                }
            #pragma unroll
            for (int np = 0; np < 2; np++)
                #pragma unroll
                for (int mt = 0; mt < 2; mt++) {
                    mma16816(s[mt][np*2+0], qh[mt], kl[np][0], kl[np][2]);
                    mma16816(s[mt][np*2+1], qh[mt], kl[np][1], kl[np][3]);
                }
        }
        __syncthreads();                       // all warps done reading K
        if (c + 1 < 16) { prefetchK(c + 1); CP_COMMIT(); }

        // ---- P = 2^S, row sums, P -> smem ----
        #pragma unroll
        for (int mt = 0; mt < 2; mt++) {
            float rs0 = 0.f, rs1 = 0.f;
            const int prow = wm*32 + mt*16 + (lane >> 2);
            #pragma unroll
            for (int nt = 0; nt < 4; nt++) {
                const float e0 = fast_exp2(s[mt][nt][0]);
                const float e1 = fast_exp2(s[mt][nt][1]);
                const float e2 = fast_exp2(s[mt][nt][2]);
                const float e3 = fast_exp2(s[mt][nt][3]);
                rs0 += e0 + e1;
                rs1 += e2 + e3;
                const int pcol = wn*32 + nt*8 + (lane & 3)*2;
                const uint32_t off0 = (uint32_t)(prow*144 + pcol*2);
                split2_store(smem + A_PHI + off0, smem + A_PLO + off0, e0, e1);
                const uint32_t off1 = off0 + 8*144;
                split2_store(smem + A_PHI + off1, smem + A_PLO + off1, e2, e3);
            }
            rs0 += __shfl_xor_sync(0xffffffffu, rs0, 1);
            rs0 += __shfl_xor_sync(0xffffffffu, rs0, 2);
            rs1 += __shfl_xor_sync(0xffffffffu, rs1, 1);
            rs1 += __shfl_xor_sync(0xffffffffu, rs1, 2);
            if ((lane & 3) == 0) {
                rsp[wn*128 + prow]     = rs0;
                rsp[wn*128 + prow + 8] = rs1;
            }
        }
        __syncthreads();
        if (tid < 128) rsa[tid] += rsp[tid] + rsp[128 + tid];

        // ---- O += P @ V (3-pass) ----
        #pragma unroll
        for (int ks = 0; ks < 4; ks++) {
            uint32_t ph[2][4], pl[2][4];
            ldsm4(aPhi + ks*32,                          ph[0]);
            ldsm4(aPhi + 16*144 + ks*32,                 ph[1]);
            ldsm4(aPhi + (A_PLO-A_PHI) + ks*32,          pl[0]);
            ldsm4(aPhi + (A_PLO-A_PHI) + 16*144 + ks*32, pl[1]);
            uint32_t vh[2][4], vl[2][4];
            #pragma unroll
            for (int np = 0; np < 2; np++) {
                ldsm4t(aVhi + ks*16*144 + np*32,                 vh[np]);
                ldsm4t(aVhi + (A_VLO-A_VHI) + ks*16*144 + np*32, vl[np]);
            }
            #pragma unroll
            for (int np = 0; np < 2; np++)
                #pragma unroll
                for (int mt = 0; mt < 2; mt++) {
                    mma16816(o[mt][np*2+0], ph[mt], vh[np][0], vh[np][1]);
                    mma16816(o[mt][np*2+1], ph[mt], vh[np][2], vh[np][3]);
                }
            #pragma unroll
            for (int np = 0; np < 2; np++)
                #pragma unroll
                for (int mt = 0; mt < 2; mt++) {
                    mma16816(o[mt][np*2+0], pl[mt], vh[np][0], vh[np][1]);
                    mma16816(o[mt][np*2+1], pl[mt], vh[np][2], vh[np][3]);
                }
            #pragma unroll
            for (int np = 0; np < 2; np++)
                #pragma unroll
                for (int mt = 0; mt < 2; mt++) {
                    mma16816(o[mt][np*2+0], ph[mt], vl[np][0], vl[np][1]);
                    mma16816(o[mt][np*2+1], ph[mt], vl[np][2], vl[np][3]);
                }
        }
        __syncthreads();                       // all warps done reading V + P
        if (c + 1 < 16) { prefetchV(c + 1); CP_COMMIT(); }
    }

    // Normalize + split-store AO
    const int b = bh / HEADS;
    const int h = bh - b*HEADS;
    #pragma unroll
    for (int mt = 0; mt < 2; mt++) {
        const int row0 = wm*32 + mt*16 + (lane >> 2);
        const float inv0 = 1.f / rsa[row0];
        const float inv1 = 1.f / rsa[row0 + 8];
        #pragma unroll
        for (int nt = 0; nt < 4; nt++) {
            const int d = wn*32 + nt*8 + (lane & 3)*2;
            {
                const size_t idx = (size_t)(b*SEQ + q0 + row0)*INNER + h*DHEAD + d;
                __nv_bfloat162 h2, l2;
                split_pack(o[mt][nt][0]*inv0, o[mt][nt][1]*inv0, h2, l2);
                *(__nv_bfloat162*)(g_AOhi + idx) = h2;
                *(__nv_bfloat162*)(g_AOlo + idx) = l2;
            }
            {
                const size_t idx = (size_t)(b*SEQ + q0 + row0 + 8)*INNER + h*DHEAD + d;
                __nv_bfloat162 h2, l2;
                split_pack(o[mt][nt][2]*inv1, o[mt][nt][3]*inv1, h2, l2);
                *(__nv_bfloat162*)(g_AOhi + idx) = h2;
                *(__nv_bfloat162*)(g_AOlo + idx) = l2;
            }
        }
    }
}

// ---------------------------------------------------------------------------
// Launch
// ---------------------------------------------------------------------------
extern "C" void kernel_launch(void* const* d_in, const int* in_sizes, int n_in,
                              void* d_out, int out_size)
{
    const float* x     = (const float*)d_in[0];
    const float* w_qkv = (const float*)d_in[1];
    const float* w_out = (const float*)d_in[2];
    const float* b_out = (const float*)d_in[3];
    float* out = (float*)d_out;

    cudaFuncSetAttribute(gemm_tc<0>, cudaFuncAttributeMaxDynamicSharedMemorySize, G_SMEM_BYTES);
    cudaFuncSetAttribute(gemm_tc<1>, cudaFuncAttributeMaxDynamicSharedMemorySize, G_SMEM_BYTES);
    cudaFuncSetAttribute(attn_tc,    cudaFuncAttributeMaxDynamicSharedMemorySize, A_SMEM_BYTES);

    cvt_split<0><<<(MROWS*DIM)/1024, 256>>>(x, MROWS*DIM);
    cvt_split<1><<<(DIM*NQKV)/1024, 256>>>(w_qkv, DIM*NQKV);
    cvt_split<2><<<(INNER*DIM)/1024, 256>>>(w_out, INNER*DIM);

    dim3 g1(NQKV/128, MROWS/128);   // 18 x 64
    gemm_tc<0><<<g1, 256, G_SMEM_BYTES>>>(nullptr, nullptr);

    dim3 g2(SEQ/128, BATCH*HEADS);  // 8 x 96
    attn_tc<<<g2, 256, A_SMEM_BYTES>>>();

    dim3 g3(DIM/128, MROWS/128);    // 6 x 64
    gemm_tc<1><<<g3, 256, G_SMEM_BYTES>>>(b_out, out);
}

// round 9
// speedup vs baseline: 1.6336x; 1.4627x over previous
#include <cuda_runtime.h>
#include <cuda_fp16.h>
#include <cstdint>
#include <math.h>

#define BATCH   8
#define SEQ     1024
#define DIM     768
#define HEADS   12
#define DHEAD   64
#define INNER   768
#define NQKV    2304
#define MROWS   8192
#define SC_LOG2E 0.1803368801111244f

// ---------------------------------------------------------------------------
// Persistent fp16 scratch.  Split tensors: x ~= hi + lo (fp16 each, ~22 bits).
// Single tensors: plain fp16 (2^-12 rounding — the error budget driver).
// ---------------------------------------------------------------------------
__device__ __half g_Xhi[MROWS*DIM],  g_Xlo[MROWS*DIM];
__device__ __half g_WQs[DIM*NQKV];                      // single
__device__ __half g_WOs[INNER*DIM];                     // single
__device__ __half g_Qhi[BATCH*HEADS*SEQ*DHEAD], g_Qlo[BATCH*HEADS*SEQ*DHEAD];
__device__ __half g_Ks [BATCH*HEADS*SEQ*DHEAD];         // single
__device__ __half g_Vhi[BATCH*HEADS*SEQ*DHEAD], g_Vlo[BATCH*HEADS*SEQ*DHEAD];
__device__ __half g_AOhi[MROWS*INNER], g_AOlo[MROWS*INNER];

// ---------------------------------------------------------------------------
// Helpers
// ---------------------------------------------------------------------------
__device__ __forceinline__ uint32_t smem_u32(const void* p) {
    uint32_t a;
    asm("{ .reg .u64 t; cvta.to.shared.u64 t, %1; cvt.u32.u64 %0, t; }" : "=r"(a) : "l"(p));
    return a;
}
__device__ __forceinline__ void ldsm4(uint32_t addr, uint32_t* r) {
    asm volatile("ldmatrix.sync.aligned.m8n8.x4.shared.b16 {%0,%1,%2,%3}, [%4];"
                 : "=r"(r[0]), "=r"(r[1]), "=r"(r[2]), "=r"(r[3]) : "r"(addr));
}
__device__ __forceinline__ void ldsm4t(uint32_t addr, uint32_t* r) {
    asm volatile("ldmatrix.sync.aligned.m8n8.x4.trans.shared.b16 {%0,%1,%2,%3}, [%4];"
                 : "=r"(r[0]), "=r"(r[1]), "=r"(r[2]), "=r"(r[3]) : "r"(addr));
}
__device__ __forceinline__ void mma16816(float* c, const uint32_t* a, uint32_t b0, uint32_t b1) {
    asm volatile("mma.sync.aligned.m16n8k16.row.col.f32.f16.f16.f32 "
                 "{%0,%1,%2,%3}, {%4,%5,%6,%7}, {%8,%9}, {%0,%1,%2,%3};"
                 : "+f"(c[0]), "+f"(c[1]), "+f"(c[2]), "+f"(c[3])
                 : "r"(a[0]), "r"(a[1]), "r"(a[2]), "r"(a[3]), "r"(b0), "r"(b1));
}
__device__ __forceinline__ float fast_exp2(float x) {
    float y;
    asm("ex2.approx.f32 %0, %1;" : "=f"(y) : "f"(x));
    return y;
}
__device__ __forceinline__ void cpa16(uint32_t dst, const void* src) {
    asm volatile("cp.async.cg.shared.global [%0], [%1], 16;" :: "r"(dst), "l"(src));
}
#define CP_COMMIT() asm volatile("cp.async.commit_group;" ::: "memory")

__device__ __forceinline__ void split_pack_h(float x, float y, __half2& h2, __half2& l2) {
    __half hx = __float2half_rn(x);
    __half hy = __float2half_rn(y);
    h2 = __halves2half2(hx, hy);
    l2 = __halves2half2(__float2half_rn(x - __half2float(hx)),
                        __float2half_rn(y - __half2float(hy)));
}

// ---------------------------------------------------------------------------
// Pre-convert. SEL 0: X -> split hi/lo.  SEL 1: Wqkv single.  SEL 2: Wout single.
// ---------------------------------------------------------------------------
template<int SEL>
__global__ void cvt_split(const float* __restrict__ src, int n)
{
    const int i = (blockIdx.x * blockDim.x + threadIdx.x) * 4;
    if (i >= n) return;
    float4 v = *(const float4*)(src + i);
    if (SEL == 0) {
        __half2 h0, l0, h1, l1;
        split_pack_h(v.x, v.y, h0, l0);
        split_pack_h(v.z, v.w, h1, l1);
        *(__half2*)(g_Xhi + i)     = h0;
        *(__half2*)(g_Xhi + i + 2) = h1;
        *(__half2*)(g_Xlo + i)     = l0;
        *(__half2*)(g_Xlo + i + 2) = l1;
    } else {
        __half* dst = (SEL == 1) ? g_WQs : g_WOs;
        *(__half2*)(dst + i)     = __halves2half2(__float2half_rn(v.x), __float2half_rn(v.y));
        *(__half2*)(dst + i + 2) = __halves2half2(__float2half_rn(v.z), __float2half_rn(v.w));
    }
}

// ---------------------------------------------------------------------------
// GEMM: 2-pass fp16 (A split hi/lo, B single), K-chunk 64, double-buffered,
// 2 CTAs/SM. A stage rows 144B (64 fp16 + pad), B stage rows 272B.
// MODE 0: X @ Wqkv -> scatter Q(split,scaled)/K(single)/V(split)
// MODE 1: AO @ Wout + bias -> fp32 out
// ---------------------------------------------------------------------------
#define G_AHI 0
#define G_ALO 18432
#define G_B   36864
#define G_STAGE 54272
#define G_SMEM_BYTES (2*G_STAGE)   // 108544

template<int MODE>
__global__ void __launch_bounds__(256, 2)
gemm_tc(const float* __restrict__ bias, float* __restrict__ out)
{
    extern __shared__ char smem[];
    const uint32_t sb = smem_u32(smem);
    const int tid  = threadIdx.x;
    const int lane = tid & 31;
    const int wid  = tid >> 5;
    const int wm   = wid & 3;
    const int wn   = wid >> 2;
    const int bx = blockIdx.x, by = blockIdx.y;

    const __half* Ahi = (MODE == 0) ? g_Xhi : g_AOhi;
    const __half* Alo = (MODE == 0) ? g_Xlo : g_AOlo;
    const __half* Bs  = (MODE == 0) ? g_WQs : g_WOs;
    const int ldb = (MODE == 0) ? NQKV : DIM;

    float acc[2][8][4];
    #pragma unroll
    for (int i = 0; i < 2; i++)
        #pragma unroll
        for (int j = 0; j < 8; j++)
            #pragma unroll
            for (int k = 0; k < 4; k++) acc[i][j][k] = 0.f;

    const int lrow = lane & 15;
    const int lc16 = (lane >> 4) * 16;
    const uint32_t aA = sb + G_AHI + (uint32_t)((wm*32 + lrow)*144) + lc16;
    const uint32_t aB = sb + G_B   + (uint32_t)(lrow*272) + (uint32_t)(wn*128) + lc16;

    auto prefetch = [&](int ch, int st) {
        const int k0 = ch * 64;
        const uint32_t sa = sb + (uint32_t)st * G_STAGE;
        #pragma unroll
        for (int i = tid; i < 1024; i += 256) {
            const int row = i >> 3, seg = i & 7;
            const uint32_t d = sa + G_AHI + row*144 + seg*16;
            const size_t g = (size_t)(by*128 + row)*768 + k0 + seg*8;
            cpa16(d,                 Ahi + g);
            cpa16(d + (G_ALO-G_AHI), Alo + g);
        }
        #pragma unroll
        for (int i = tid; i < 1024; i += 256) {
            const int row = i >> 4, seg = i & 15;
            const uint32_t d = sa + G_B + row*272 + seg*16;
            const size_t g = (size_t)(k0 + row)*ldb + bx*128 + seg*8;
            cpa16(d, Bs + g);
        }
    };

    prefetch(0, 0);
    CP_COMMIT();

    for (int ch = 0; ch < 12; ch++) {
        if (ch + 1 < 12) { prefetch(ch + 1, (ch + 1) & 1); CP_COMMIT(); }
        if (ch + 1 < 12) { asm volatile("cp.async.wait_group 1;" ::: "memory"); }
        else             { asm volatile("cp.async.wait_group 0;" ::: "memory"); }
        __syncthreads();

        const uint32_t so = (uint32_t)(ch & 1) * G_STAGE;
        #pragma unroll
        for (int ks = 0; ks < 4; ks++) {
            uint32_t ah[2][4], al[2][4];
            ldsm4(aA + so + ks*32,                          ah[0]);
            ldsm4(aA + so + 16*144 + ks*32,                 ah[1]);
            ldsm4(aA + so + (G_ALO-G_AHI) + ks*32,          al[0]);
            ldsm4(aA + so + (G_ALO-G_AHI) + 16*144 + ks*32, al[1]);
            uint32_t bh[4][4];
            #pragma unroll
            for (int np = 0; np < 4; np++)
                ldsm4t(aB + so + ks*4352 + np*32, bh[np]);
            // hi pass
            #pragma unroll
            for (int np = 0; np < 4; np++)
                #pragma unroll
                for (int mt = 0; mt < 2; mt++) {
                    mma16816(acc[mt][np*2+0], ah[mt], bh[np][0], bh[np][1]);
                    mma16816(acc[mt][np*2+1], ah[mt], bh[np][2], bh[np][3]);
                }
            // lo pass
            #pragma unroll
            for (int np = 0; np < 4; np++)
                #pragma unroll
                for (int mt = 0; mt < 2; mt++) {
                    mma16816(acc[mt][np*2+0], al[mt], bh[np][0], bh[np][1]);
                    mma16816(acc[mt][np*2+1], al[mt], bh[np][2], bh[np][3]);
                }
        }
        __syncthreads();
    }

    // Epilogue
    #pragma unroll
    for (int mt = 0; mt < 2; mt++) {
        const int row0 = by*128 + wm*32 + mt*16 + (lane >> 2);
        #pragma unroll
        for (int nt = 0; nt < 8; nt++) {
            const int col = bx*128 + wn*64 + nt*8 + (lane & 3)*2;
            if (MODE == 0) {
                const int sel = col / INNER;
                const int cr = col - sel*INNER;
                const int h = cr >> 6, d = cr & 63;
                #pragma unroll
                for (int rr = 0; rr < 2; rr++) {
                    const int r = row0 + rr*8;
                    const int b = r >> 10, nn = r & 1023;
                    const size_t idx = (size_t)(((b*HEADS + h) << 10) + nn)*DHEAD + d;
                    const float v0 = acc[mt][nt][rr*2+0];
                    const float v1 = acc[mt][nt][rr*2+1];
                    if (sel == 1) {
                        *(__half2*)(g_Ks + idx) =
                            __halves2half2(__float2half_rn(v0), __float2half_rn(v1));
                    } else {
                        const float sc = (sel == 0) ? SC_LOG2E : 1.f;
                        __half* dhi = (sel == 0) ? g_Qhi : g_Vhi;
                        __half* dlo = (sel == 0) ? g_Qlo : g_Vlo;
                        __half2 h2, l2;
                        split_pack_h(v0*sc, v1*sc, h2, l2);
                        *(__half2*)(dhi + idx) = h2;
                        *(__half2*)(dlo + idx) = l2;
                    }
                }
            } else {
                const float b0 = bias[col], b1 = bias[col+1];
                *(float2*)&out[(size_t)row0*DIM + col] =
                    make_float2(acc[mt][nt][0] + b0, acc[mt][nt][1] + b1);
                *(float2*)&out[(size_t)(row0+8)*DIM + col] =
                    make_float2(acc[mt][nt][2] + b0, acc[mt][nt][3] + b1);
            }
        }
    }
}

// ---------------------------------------------------------------------------
// Attention: 2-pass fp16 (Q split + K single; P single + V split),
// K/V double-buffered, 2 CTAs/SM. 128 q/CTA, 16 chunks of 64 keys, 8 warps.
// ---------------------------------------------------------------------------
#define A_QHI 0
#define A_QLO 18432
#define A_PS  36864
#define A_RSP 55296
#define A_RSA 56320
#define A_KV0 56832
#define A_KSo  0
#define A_VHIo 9216
#define A_VLOo 18432
#define A_KVSTAGE 27648
#define A_SMEM_BYTES 112128

__global__ void __launch_bounds__(256, 2)
attn_tc()
{
    extern __shared__ char smem[];
    const uint32_t sb = smem_u32(smem);
    const int tid  = threadIdx.x;
    const int lane = tid & 31;
    const int wid  = tid >> 5;
    const int wm   = wid & 3;
    const int wn   = wid >> 2;
    const int bh = blockIdx.y;
    const int q0 = blockIdx.x * 128;

    float* rsp = (float*)(smem + A_RSP);
    float* rsa = (float*)(smem + A_RSA);
    if (tid < 128) rsa[tid] = 0.f;

    const size_t base = (size_t)bh * SEQ * DHEAD;

    auto prefetchKV = [&](int c, int st) {
        const size_t g0 = base + (size_t)c*64*DHEAD;
        const uint32_t sa = sb + A_KV0 + (uint32_t)st * A_KVSTAGE;
        #pragma unroll
        for (int i = tid; i < 512; i += 256) {
            const int row = i >> 3, seg = i & 7;
            const uint32_t d = sa + row*144 + seg*16;
            const size_t g = g0 + row*64 + seg*8;
            cpa16(d + A_KSo,  g_Ks  + g);
            cpa16(d + A_VHIo, g_Vhi + g);
            cpa16(d + A_VLOo, g_Vlo + g);
        }
    };

    // Q (split) + first K/V chunk
    #pragma unroll
    for (int i = tid; i < 1024; i += 256) {
        const int row = i >> 3, seg = i & 7;
        const uint32_t d = sb + A_QHI + row*144 + seg*16;
        const size_t g = base + (size_t)(q0 + row)*DHEAD + seg*8;
        cpa16(d,                 g_Qhi + g);
        cpa16(d + (A_QLO-A_QHI), g_Qlo + g);
    }
    prefetchKV(0, 0);
    CP_COMMIT();

    float o[2][4][4];
    #pragma unroll
    for (int i = 0; i < 2; i++)
        #pragma unroll
        for (int j = 0; j < 4; j++)
            #pragma unroll
            for (int k = 0; k < 4; k++) o[i][j][k] = 0.f;

    const int lrow = lane & 15;
    const int lc16 = (lane >> 4) * 16;
    const uint32_t aQ = sb + A_QHI + (uint32_t)((wm*32 + lrow)*144) + lc16;
    const uint32_t aK = sb + A_KV0 + A_KSo  + (uint32_t)((wn*32 + lrow)*144) + lc16;
    const uint32_t aV = sb + A_KV0 + A_VHIo + (uint32_t)(lrow*144) + (uint32_t)(wn*64) + lc16;
    const uint32_t aP = sb + A_PS  + (uint32_t)((wm*32 + lrow)*144) + lc16;

    for (int c = 0; c < 16; c++) {
        if (c + 1 < 16) { prefetchKV(c + 1, (c + 1) & 1); CP_COMMIT(); }
        if (c + 1 < 16) { asm volatile("cp.async.wait_group 1;" ::: "memory"); }
        else            { asm volatile("cp.async.wait_group 0;" ::: "memory"); }
        __syncthreads();

        const uint32_t so = (uint32_t)(c & 1) * A_KVSTAGE;

        // ---- S = Q @ K^T (2 passes: Qhi, Qlo; K single) ----
        float s[2][4][4];
        #pragma unroll
        for (int i = 0; i < 2; i++)
            #pragma unroll
            for (int j = 0; j < 4; j++)
                #pragma unroll
                for (int k = 0; k < 4; k++) s[i][j][k] = 0.f;

        #pragma unroll
        for (int ks = 0; ks < 4; ks++) {
            uint32_t qh[2][4], ql[2][4];
            ldsm4(aQ + ks*32,                          qh[0]);
            ldsm4(aQ + 16*144 + ks*32,                 qh[1]);
            ldsm4(aQ + (A_QLO-A_QHI) + ks*32,          ql[0]);
            ldsm4(aQ + (A_QLO-A_QHI) + 16*144 + ks*32, ql[1]);
            uint32_t kh[2][4];
            #pragma unroll
            for (int np = 0; np < 2; np++)
                ldsm4(aK + so + np*16*144 + ks*32, kh[np]);
            // non-trans pairing: {r0,r2} / {r1,r3}
            #pragma unroll
            for (int np = 0; np < 2; np++)
                #pragma unroll
                for (int mt = 0; mt < 2; mt++) {
                    mma16816(s[mt][np*2+0], qh[mt], kh[np][0], kh[np][2]);
                    mma16816(s[mt][np*2+1], qh[mt], kh[np][1], kh[np][3]);
                }
            #pragma unroll
            for (int np = 0; np < 2; np++)
                #pragma unroll
                for (int mt = 0; mt < 2; mt++) {
                    mma16816(s[mt][np*2+0], ql[mt], kh[np][0], kh[np][2]);
                    mma16816(s[mt][np*2+1], ql[mt], kh[np][1], kh[np][3]);
                }
        }

        // ---- P = 2^S (single fp16), row sums ----
        #pragma unroll
        for (int mt = 0; mt < 2; mt++) {
            float rs0 = 0.f, rs1 = 0.f;
            const int prow = wm*32 + mt*16 + (lane >> 2);
            #pragma unroll
            for (int nt = 0; nt < 4; nt++) {
                const float e0 = fast_exp2(s[mt][nt][0]);
                const float e1 = fast_exp2(s[mt][nt][1]);
                const float e2 = fast_exp2(s[mt][nt][2]);
                const float e3 = fast_exp2(s[mt][nt][3]);
                rs0 += e0 + e1;
                rs1 += e2 + e3;
                const int pcol = wn*32 + nt*8 + (lane & 3)*2;
                const uint32_t off0 = (uint32_t)(prow*144 + pcol*2);
                *(__half2*)(smem + A_PS + off0) =
                    __halves2half2(__float2half_rn(e0), __float2half_rn(e1));
                *(__half2*)(smem + A_PS + off0 + 8*144) =
                    __halves2half2(__float2half_rn(e2), __float2half_rn(e3));
            }
            rs0 += __shfl_xor_sync(0xffffffffu, rs0, 1);
            rs0 += __shfl_xor_sync(0xffffffffu, rs0, 2);
            rs1 += __shfl_xor_sync(0xffffffffu, rs1, 1);
            rs1 += __shfl_xor_sync(0xffffffffu, rs1, 2);
            if ((lane & 3) == 0) {
                rsp[wn*128 + prow]     = rs0;
                rsp[wn*128 + prow + 8] = rs1;
            }
        }
        __syncthreads();
        if (tid < 128) rsa[tid] += rsp[tid] + rsp[128 + tid];

        // ---- O += P @ V (2 passes: Vhi, Vlo; P single) ----
        #pragma unroll
        for (int ks = 0; ks < 4; ks++) {
            uint32_t ph[2][4];
            ldsm4(aP + ks*32,          ph[0]);
            ldsm4(aP + 16*144 + ks*32, ph[1]);
            uint32_t vh[2][4], vl[2][4];
            #pragma unroll
            for (int np = 0; np < 2; np++) {
                ldsm4t(aV + so + ks*16*144 + np*32,                   vh[np]);
                ldsm4t(aV + so + (A_VLOo-A_VHIo) + ks*16*144 + np*32, vl[np]);
            }
            // trans pairing: {r0,r1} / {r2,r3}
            #pragma unroll
            for (int np = 0; np < 2; np++)
                #pragma unroll
                for (int mt = 0; mt < 2; mt++) {
                    mma16816(o[mt][np*2+0], ph[mt], vh[np][0], vh[np][1]);
                    mma16816(o[mt][np*2+1], ph[mt], vh[np][2], vh[np][3]);
                }
            #pragma unroll
            for (int np = 0; np < 2; np++)
                #pragma unroll
                for (int mt = 0; mt < 2; mt++) {
                    mma16816(o[mt][np*2+0], ph[mt], vl[np][0], vl[np][1]);
                    mma16816(o[mt][np*2+1], ph[mt], vl[np][2], vl[np][3]);
                }
        }
        __syncthreads();   // stage + P reads done before next prefetch/overwrite
    }

    // Normalize + split-store AO (fp16 hi/lo)
    const int b = bh / HEADS;
    const int h = bh - b*HEADS;
    #pragma unroll
    for (int mt = 0; mt < 2; mt++) {
        const int row0 = wm*32 + mt*16 + (lane >> 2);
        const float inv0 = 1.f / rsa[row0];
        const float inv1 = 1.f / rsa[row0 + 8];
        #pragma unroll
        for (int nt = 0; nt < 4; nt++) {
            const int d = wn*32 + nt*8 + (lane & 3)*2;
            {
                const size_t idx = (size_t)(b*SEQ + q0 + row0)*INNER + h*DHEAD + d;
                __half2 h2, l2;
                split_pack_h(o[mt][nt][0]*inv0, o[mt][nt][1]*inv0, h2, l2);
                *(__half2*)(g_AOhi + idx) = h2;
                *(__half2*)(g_AOlo + idx) = l2;
            }
            {
                const size_t idx = (size_t)(b*SEQ + q0 + row0 + 8)*INNER + h*DHEAD + d;
                __half2 h2, l2;
                split_pack_h(o[mt][nt][2]*inv1, o[mt][nt][3]*inv1, h2, l2);
                *(__half2*)(g_AOhi + idx) = h2;
                *(__half2*)(g_AOlo + idx) = l2;
            }
        }
    }
}

// ---------------------------------------------------------------------------
// Launch
// ---------------------------------------------------------------------------
extern "C" void kernel_launch(void* const* d_in, const int* in_sizes, int n_in,
                              void* d_out, int out_size)
{
    const float* x     = (const float*)d_in[0];
    const float* w_qkv = (const float*)d_in[1];
    const float* w_out = (const float*)d_in[2];
    const float* b_out = (const float*)d_in[3];
    float* out = (float*)d_out;

    cudaFuncSetAttribute(gemm_tc<0>, cudaFuncAttributeMaxDynamicSharedMemorySize, G_SMEM_BYTES);
    cudaFuncSetAttribute(gemm_tc<1>, cudaFuncAttributeMaxDynamicSharedMemorySize, G_SMEM_BYTES);
    cudaFuncSetAttribute(attn_tc,    cudaFuncAttributeMaxDynamicSharedMemorySize, A_SMEM_BYTES);

    cvt_split<0><<<(MROWS*DIM)/1024, 256>>>(x, MROWS*DIM);
    cvt_split<1><<<(DIM*NQKV)/1024, 256>>>(w_qkv, DIM*NQKV);
    cvt_split<2><<<(INNER*DIM)/1024, 256>>>(w_out, INNER*DIM);

    dim3 g1(NQKV/128, MROWS/128);   // 18 x 64
    gemm_tc<0><<<g1, 256, G_SMEM_BYTES>>>(nullptr, nullptr);

    dim3 g2(SEQ/128, BATCH*HEADS);  // 8 x 96
    attn_tc<<<g2, 256, A_SMEM_BYTES>>>();

    dim3 g3(DIM/128, MROWS/128);    // 6 x 64
    gemm_tc<1><<<g3, 256, G_SMEM_BYTES>>>(b_out, out);
}

// round 10
// speedup vs baseline: 1.6993x; 1.0403x over previous
#include <cuda_runtime.h>
#include <cuda_fp16.h>
#include <cstdint>
#include <math.h>

#define BATCH   8
#define SEQ     1024
#define DIM     768
#define HEADS   12
#define DHEAD   64
#define INNER   768
#define NQKV    2304
#define MROWS   8192
#define SC_LOG2E 0.1803368801111244f

// ---------------------------------------------------------------------------
// Persistent fp16 scratch.  Split tensors: x ~= hi + lo.  Singles: plain fp16.
// ---------------------------------------------------------------------------
__device__ __half g_Xhi[MROWS*DIM],  g_Xlo[MROWS*DIM];
__device__ __half g_WQs[DIM*NQKV];
__device__ __half g_WOs[INNER*DIM];
__device__ __half g_Qhi[BATCH*HEADS*SEQ*DHEAD], g_Qlo[BATCH*HEADS*SEQ*DHEAD];
__device__ __half g_Ks [BATCH*HEADS*SEQ*DHEAD];
__device__ __half g_Vhi[BATCH*HEADS*SEQ*DHEAD], g_Vlo[BATCH*HEADS*SEQ*DHEAD];
__device__ __half g_AOhi[MROWS*INNER], g_AOlo[MROWS*INNER];

// ---------------------------------------------------------------------------
// Helpers
// ---------------------------------------------------------------------------
__device__ __forceinline__ uint32_t smem_u32(const void* p) {
    uint32_t a;
    asm("{ .reg .u64 t; cvta.to.shared.u64 t, %1; cvt.u32.u64 %0, t; }" : "=r"(a) : "l"(p));
    return a;
}
__device__ __forceinline__ void ldsm4(uint32_t addr, uint32_t* r) {
    asm volatile("ldmatrix.sync.aligned.m8n8.x4.shared.b16 {%0,%1,%2,%3}, [%4];"
                 : "=r"(r[0]), "=r"(r[1]), "=r"(r[2]), "=r"(r[3]) : "r"(addr));
}
__device__ __forceinline__ void ldsm4t(uint32_t addr, uint32_t* r) {
    asm volatile("ldmatrix.sync.aligned.m8n8.x4.trans.shared.b16 {%0,%1,%2,%3}, [%4];"
                 : "=r"(r[0]), "=r"(r[1]), "=r"(r[2]), "=r"(r[3]) : "r"(addr));
}
__device__ __forceinline__ void mma16816(float* c, const uint32_t* a, uint32_t b0, uint32_t b1) {
    asm volatile("mma.sync.aligned.m16n8k16.row.col.f32.f16.f16.f32 "
                 "{%0,%1,%2,%3}, {%4,%5,%6,%7}, {%8,%9}, {%0,%1,%2,%3};"
                 : "+f"(c[0]), "+f"(c[1]), "+f"(c[2]), "+f"(c[3])
                 : "r"(a[0]), "r"(a[1]), "r"(a[2]), "r"(a[3]), "r"(b0), "r"(b1));
}
__device__ __forceinline__ float fast_exp2(float x) {
    float y;
    asm("ex2.approx.f32 %0, %1;" : "=f"(y) : "f"(x));
    return y;
}
__device__ __forceinline__ void cpa16(uint32_t dst, const void* src) {
    asm volatile("cp.async.cg.shared.global [%0], [%1], 16;" :: "r"(dst), "l"(src));
}
#define CP_COMMIT() asm volatile("cp.async.commit_group;" ::: "memory")

__device__ __forceinline__ void split_pack_h(float x, float y, __half2& h2, __half2& l2) {
    __half hx = __float2half_rn(x);
    __half hy = __float2half_rn(y);
    h2 = __halves2half2(hx, hy);
    l2 = __halves2half2(__float2half_rn(x - __half2float(hx)),
                        __float2half_rn(y - __half2float(hy)));
}
__device__ __forceinline__ uint32_t pack_h2(float x, float y) {
    __half2 h = __halves2half2(__float2half_rn(x), __float2half_rn(y));
    uint32_t r;
    r = *reinterpret_cast<uint32_t*>(&h);
    return r;
}

// ---------------------------------------------------------------------------
// Pre-convert. SEL 0: X -> split hi/lo.  SEL 1: Wqkv single.  SEL 2: Wout single.
// ---------------------------------------------------------------------------
template<int SEL>
__global__ void cvt_split(const float* __restrict__ src, int n)
{
    const int i = (blockIdx.x * blockDim.x + threadIdx.x) * 4;
    if (i >= n) return;
    float4 v = *(const float4*)(src + i);
    if (SEL == 0) {
        __half2 h0, l0, h1, l1;
        split_pack_h(v.x, v.y, h0, l0);
        split_pack_h(v.z, v.w, h1, l1);
        *(__half2*)(g_Xhi + i)     = h0;
        *(__half2*)(g_Xhi + i + 2) = h1;
        *(__half2*)(g_Xlo + i)     = l0;
        *(__half2*)(g_Xlo + i + 2) = l1;
    } else {
        __half* dst = (SEL == 1) ? g_WQs : g_WOs;
        *(__half2*)(dst + i)     = __halves2half2(__float2half_rn(v.x), __float2half_rn(v.y));
        *(__half2*)(dst + i + 2) = __halves2half2(__float2half_rn(v.z), __float2half_rn(v.w));
    }
}

// ---------------------------------------------------------------------------
// GEMM: 2-pass fp16 (A split hi/lo, B single), K-chunk 64, double-buffered,
// 2 CTAs/SM.  (unchanged from R9)
// ---------------------------------------------------------------------------
#define G_AHI 0
#define G_ALO 18432
#define G_B   36864
#define G_STAGE 54272
#define G_SMEM_BYTES (2*G_STAGE)   // 108544

template<int MODE>
__global__ void __launch_bounds__(256, 2)
gemm_tc(const float* __restrict__ bias, float* __restrict__ out)
{
    extern __shared__ char smem[];
    const uint32_t sb = smem_u32(smem);
    const int tid  = threadIdx.x;
    const int lane = tid & 31;
    const int wid  = tid >> 5;
    const int wm   = wid & 3;
    const int wn   = wid >> 2;
    const int bx = blockIdx.x, by = blockIdx.y;

    const __half* Ahi = (MODE == 0) ? g_Xhi : g_AOhi;
    const __half* Alo = (MODE == 0) ? g_Xlo : g_AOlo;
    const __half* Bs  = (MODE == 0) ? g_WQs : g_WOs;
    const int ldb = (MODE == 0) ? NQKV : DIM;

    float acc[2][8][4];
    #pragma unroll
    for (int i = 0; i < 2; i++)
        #pragma unroll
        for (int j = 0; j < 8; j++)
            #pragma unroll
            for (int k = 0; k < 4; k++) acc[i][j][k] = 0.f;

    const int lrow = lane & 15;
    const int lc16 = (lane >> 4) * 16;
    const uint32_t aA = sb + G_AHI + (uint32_t)((wm*32 + lrow)*144) + lc16;
    const uint32_t aB = sb + G_B   + (uint32_t)(lrow*272) + (uint32_t)(wn*128) + lc16;

    auto prefetch = [&](int ch, int st) {
        const int k0 = ch * 64;
        const uint32_t sa = sb + (uint32_t)st * G_STAGE;
        #pragma unroll
        for (int i = tid; i < 1024; i += 256) {
            const int row = i >> 3, seg = i & 7;
            const uint32_t d = sa + G_AHI + row*144 + seg*16;
            const size_t g = (size_t)(by*128 + row)*768 + k0 + seg*8;
            cpa16(d,                 Ahi + g);
            cpa16(d + (G_ALO-G_AHI), Alo + g);
        }
        #pragma unroll
        for (int i = tid; i < 1024; i += 256) {
            const int row = i >> 4, seg = i & 15;
            const uint32_t d = sa + G_B + row*272 + seg*16;
            const size_t g = (size_t)(k0 + row)*ldb + bx*128 + seg*8;
            cpa16(d, Bs + g);
        }
    };

    prefetch(0, 0);
    CP_COMMIT();

    for (int ch = 0; ch < 12; ch++) {
        if (ch + 1 < 12) { prefetch(ch + 1, (ch + 1) & 1); CP_COMMIT(); }
        if (ch + 1 < 12) { asm volatile("cp.async.wait_group 1;" ::: "memory"); }
        else             { asm volatile("cp.async.wait_group 0;" ::: "memory"); }
        __syncthreads();

        const uint32_t so = (uint32_t)(ch & 1) * G_STAGE;
        #pragma unroll
        for (int ks = 0; ks < 4; ks++) {
            uint32_t ah[2][4], al[2][4];
            ldsm4(aA + so + ks*32,                          ah[0]);
            ldsm4(aA + so + 16*144 + ks*32,                 ah[1]);
            ldsm4(aA + so + (G_ALO-G_AHI) + ks*32,          al[0]);
            ldsm4(aA + so + (G_ALO-G_AHI) + 16*144 + ks*32, al[1]);
            uint32_t bh[4][4];
            #pragma unroll
            for (int np = 0; np < 4; np++)
                ldsm4t(aB + so + ks*4352 + np*32, bh[np]);
            #pragma unroll
            for (int np = 0; np < 4; np++)
                #pragma unroll
                for (int mt = 0; mt < 2; mt++) {
                    mma16816(acc[mt][np*2+0], ah[mt], bh[np][0], bh[np][1]);
                    mma16816(acc[mt][np*2+1], ah[mt], bh[np][2], bh[np][3]);
                }
            #pragma unroll
            for (int np = 0; np < 4; np++)
                #pragma unroll
                for (int mt = 0; mt < 2; mt++) {
                    mma16816(acc[mt][np*2+0], al[mt], bh[np][0], bh[np][1]);
                    mma16816(acc[mt][np*2+1], al[mt], bh[np][2], bh[np][3]);
                }
        }
        __syncthreads();
    }

    #pragma unroll
    for (int mt = 0; mt < 2; mt++) {
        const int row0 = by*128 + wm*32 + mt*16 + (lane >> 2);
        #pragma unroll
        for (int nt = 0; nt < 8; nt++) {
            const int col = bx*128 + wn*64 + nt*8 + (lane & 3)*2;
            if (MODE == 0) {
                const int sel = col / INNER;
                const int cr = col - sel*INNER;
                const int h = cr >> 6, d = cr & 63;
                #pragma unroll
                for (int rr = 0; rr < 2; rr++) {
                    const int r = row0 + rr*8;
                    const int b = r >> 10, nn = r & 1023;
                    const size_t idx = (size_t)(((b*HEADS + h) << 10) + nn)*DHEAD + d;
                    const float v0 = acc[mt][nt][rr*2+0];
                    const float v1 = acc[mt][nt][rr*2+1];
                    if (sel == 1) {
                        *(__half2*)(g_Ks + idx) =
                            __halves2half2(__float2half_rn(v0), __float2half_rn(v1));
                    } else {
                        const float sc = (sel == 0) ? SC_LOG2E : 1.f;
                        __half* dhi = (sel == 0) ? g_Qhi : g_Vhi;
                        __half* dlo = (sel == 0) ? g_Qlo : g_Vlo;
                        __half2 h2, l2;
                        split_pack_h(v0*sc, v1*sc, h2, l2);
                        *(__half2*)(dhi + idx) = h2;
                        *(__half2*)(dlo + idx) = l2;
                    }
                }
            } else {
                const float b0 = bias[col], b1 = bias[col+1];
                *(float2*)&out[(size_t)row0*DIM + col] =
                    make_float2(acc[mt][nt][0] + b0, acc[mt][nt][1] + b1);
                *(float2*)&out[(size_t)(row0+8)*DIM + col] =
                    make_float2(acc[mt][nt][2] + b0, acc[mt][nt][3] + b1);
            }
        }
    }
}

// ---------------------------------------------------------------------------
// Attention, P-in-registers (FA2 fragment reuse).
// 8 warps x 16 q rows each; every warp covers ALL 64 keys and ALL 64 d.
// S C-fragments -> fp16 A-fragments directly (no P smem roundtrip).
// Row sums live in registers. 2 syncs/chunk. KV double-buffered, 2 CTAs/SM.
// ---------------------------------------------------------------------------
#define A_QHI 0
#define A_QLO 18432
#define A_KV0 36864
#define A_KSo  0
#define A_VHIo 9216
#define A_VLOo 18432
#define A_KVSTAGE 27648
#define A_SMEM_BYTES (36864 + 2*27648)   // 92160

__global__ void __launch_bounds__(256, 2)
attn_tc()
{
    extern __shared__ char smem[];
    const uint32_t sb = smem_u32(smem);
    const int tid  = threadIdx.x;
    const int lane = tid & 31;
    const int wid  = tid >> 5;        // warp owns q rows wid*16 .. wid*16+15
    const int bh = blockIdx.y;
    const int q0 = blockIdx.x * 128;

    const size_t base = (size_t)bh * SEQ * DHEAD;

    auto prefetchKV = [&](int c, int st) {
        const size_t g0 = base + (size_t)c*64*DHEAD;
        const uint32_t sa = sb + A_KV0 + (uint32_t)st * A_KVSTAGE;
        #pragma unroll
        for (int i = tid; i < 512; i += 256) {
            const int row = i >> 3, seg = i & 7;
            const uint32_t d = sa + row*144 + seg*16;
            const size_t g = g0 + row*64 + seg*8;
            cpa16(d + A_KSo,  g_Ks  + g);
            cpa16(d + A_VHIo, g_Vhi + g);
            cpa16(d + A_VLOo, g_Vlo + g);
        }
    };

    // Q (split) + first K/V chunk
    #pragma unroll
    for (int i = tid; i < 1024; i += 256) {
        const int row = i >> 3, seg = i & 7;
        const uint32_t d = sb + A_QHI + row*144 + seg*16;
        const size_t g = base + (size_t)(q0 + row)*DHEAD + seg*8;
        cpa16(d,                 g_Qhi + g);
        cpa16(d + (A_QLO-A_QHI), g_Qlo + g);
    }
    prefetchKV(0, 0);
    CP_COMMIT();

    float o[8][4];
    #pragma unroll
    for (int j = 0; j < 8; j++)
        #pragma unroll
        for (int k = 0; k < 4; k++) o[j][k] = 0.f;
    float rs0 = 0.f, rs1 = 0.f;      // row sums for rows (lane>>2) and +8

    const int lrow = lane & 15;
    const int lc16 = (lane >> 4) * 16;
    const uint32_t aQ = sb + A_QHI + (uint32_t)((wid*16 + lrow)*144) + lc16;
    const uint32_t aK = sb + A_KV0 + A_KSo  + (uint32_t)(lrow*144) + lc16;
    const uint32_t aV = sb + A_KV0 + A_VHIo + (uint32_t)(lrow*144) + lc16;

    for (int c = 0; c < 16; c++) {
        if (c + 1 < 16) { prefetchKV(c + 1, (c + 1) & 1); CP_COMMIT(); }
        if (c + 1 < 16) { asm volatile("cp.async.wait_group 1;" ::: "memory"); }
        else            { asm volatile("cp.async.wait_group 0;" ::: "memory"); }
        __syncthreads();

        const uint32_t so = (uint32_t)(c & 1) * A_KVSTAGE;

        // ---- S = Q @ K^T: m16 (q) x n64 (keys), 2 passes (Qhi, Qlo) ----
        float s[8][4];
        #pragma unroll
        for (int j = 0; j < 8; j++)
            #pragma unroll
            for (int k = 0; k < 4; k++) s[j][k] = 0.f;

        #pragma unroll
        for (int ks = 0; ks < 4; ks++) {
            uint32_t qh[4], ql[4];
            ldsm4(aQ + ks*32,                 qh);
            ldsm4(aQ + (A_QLO-A_QHI) + ks*32, ql);
            uint32_t kh[4][4];
            #pragma unroll
            for (int np = 0; np < 4; np++)
                ldsm4(aK + so + np*16*144 + ks*32, kh[np]);
            // non-trans pairing: {r0,r2} / {r1,r3}
            #pragma unroll
            for (int np = 0; np < 4; np++) {
                mma16816(s[np*2+0], qh, kh[np][0], kh[np][2]);
                mma16816(s[np*2+1], qh, kh[np][1], kh[np][3]);
            }
            #pragma unroll
            for (int np = 0; np < 4; np++) {
                mma16816(s[np*2+0], ql, kh[np][0], kh[np][2]);
                mma16816(s[np*2+1], ql, kh[np][1], kh[np][3]);
            }
        }

        // ---- P = 2^S in registers: C-fragments -> fp16 A-fragments ----
        // A m16k16 frag kf covers keys kf*16..+15 = S tiles 2kf (keys 0-7) and 2kf+1.
        uint32_t pa[4][4];
        #pragma unroll
        for (int kf = 0; kf < 4; kf++) {
            const int t0 = 2*kf, t1 = 2*kf + 1;
            const float e0 = fast_exp2(s[t0][0]);
            const float e1 = fast_exp2(s[t0][1]);
            const float e2 = fast_exp2(s[t0][2]);
            const float e3 = fast_exp2(s[t0][3]);
            const float f0 = fast_exp2(s[t1][0]);
            const float f1 = fast_exp2(s[t1][1]);
            const float f2 = fast_exp2(s[t1][2]);
            const float f3 = fast_exp2(s[t1][3]);
            rs0 += e0 + e1 + f0 + f1;
            rs1 += e2 + e3 + f2 + f3;
            pa[kf][0] = pack_h2(e0, e1);   // (row,   k0-1)
            pa[kf][1] = pack_h2(e2, e3);   // (row+8, k0-1)
            pa[kf][2] = pack_h2(f0, f1);   // (row,   k8-9)
            pa[kf][3] = pack_h2(f2, f3);   // (row+8, k8-9)
        }

        // ---- O += P @ V: k = keys (4 x k16 frags), n = 64 d, 2 passes ----
        #pragma unroll
        for (int kf = 0; kf < 4; kf++) {
            uint32_t vh[4][4], vl[4][4];
            #pragma unroll
            for (int np = 0; np < 4; np++) {
                ldsm4t(aV + so + kf*16*144 + np*32,                   vh[np]);
                ldsm4t(aV + so + (A_VLOo-A_VHIo) + kf*16*144 + np*32, vl[np]);
            }
            // trans pairing: {r0,r1} / {r2,r3}
            #pragma unroll
            for (int np = 0; np < 4; np++) {
                mma16816(o[np*2+0], pa[kf], vh[np][0], vh[np][1]);
                mma16816(o[np*2+1], pa[kf], vh[np][2], vh[np][3]);
            }
            #pragma unroll
            for (int np = 0; np < 4; np++) {
                mma16816(o[np*2+0], pa[kf], vl[np][0], vl[np][1]);
                mma16816(o[np*2+1], pa[kf], vl[np][2], vl[np][3]);
            }
        }
        __syncthreads();   // stage reads done before next prefetch overwrites
    }

    // Row sums: reduce over the 4 lanes of each row group
    rs0 += __shfl_xor_sync(0xffffffffu, rs0, 1);
    rs0 += __shfl_xor_sync(0xffffffffu, rs0, 2);
    rs1 += __shfl_xor_sync(0xffffffffu, rs1, 1);
    rs1 += __shfl_xor_sync(0xffffffffu, rs1, 2);
    const float inv0 = 1.f / rs0;
    const float inv1 = 1.f / rs1;

    // Normalize + split-store AO (fp16 hi/lo)
    const int b = bh / HEADS;
    const int h = bh - b*HEADS;
    const int row0 = q0 + wid*16 + (lane >> 2);
    #pragma unroll
    for (int nt = 0; nt < 8; nt++) {
        const int d = nt*8 + (lane & 3)*2;
        {
            const size_t idx = (size_t)(b*SEQ + row0)*INNER + h*DHEAD + d;
            __half2 h2, l2;
            split_pack_h(o[nt][0]*inv0, o[nt][1]*inv0, h2, l2);
            *(__half2*)(g_AOhi + idx) = h2;
            *(__half2*)(g_AOlo + idx) = l2;
        }
        {
            const size_t idx = (size_t)(b*SEQ + row0 + 8)*INNER + h*DHEAD + d;
            __half2 h2, l2;
            split_pack_h(o[nt][2]*inv1, o[nt][3]*inv1, h2, l2);
            *(__half2*)(g_AOhi + idx) = h2;
            *(__half2*)(g_AOlo + idx) = l2;
        }
    }
}

// ---------------------------------------------------------------------------
// Launch
// ---------------------------------------------------------------------------
extern "C" void kernel_launch(void* const* d_in, const int* in_sizes, int n_in,
                              void* d_out, int out_size)
{
    const float* x     = (const float*)d_in[0];
    const float* w_qkv = (const float*)d_in[1];
    const float* w_out = (const float*)d_in[2];
    const float* b_out = (const float*)d_in[3];
    float* out = (float*)d_out;

    cudaFuncSetAttribute(gemm_tc<0>, cudaFuncAttributeMaxDynamicSharedMemorySize, G_SMEM_BYTES);
    cudaFuncSetAttribute(gemm_tc<1>, cudaFuncAttributeMaxDynamicSharedMemorySize, G_SMEM_BYTES);
    cudaFuncSetAttribute(attn_tc,    cudaFuncAttributeMaxDynamicSharedMemorySize, A_SMEM_BYTES);

    cvt_split<0><<<(MROWS*DIM)/1024, 256>>>(x, MROWS*DIM);
    cvt_split<1><<<(DIM*NQKV)/1024, 256>>>(w_qkv, DIM*NQKV);
    cvt_split<2><<<(INNER*DIM)/1024, 256>>>(w_out, INNER*DIM);

    dim3 g1(NQKV/128, MROWS/128);   // 18 x 64
    gemm_tc<0><<<g1, 256, G_SMEM_BYTES>>>(nullptr, nullptr);

    dim3 g2(SEQ/128, BATCH*HEADS);  // 8 x 96
    attn_tc<<<g2, 256, A_SMEM_BYTES>>>();

    dim3 g3(DIM/128, MROWS/128);    // 6 x 64
    gemm_tc<1><<<g3, 256, G_SMEM_BYTES>>>(b_out, out);
}

// round 11
// speedup vs baseline: 2.2032x; 1.2965x over previous
#include <cuda_runtime.h>
#include <cuda_fp16.h>
#include <cstdint>
#include <math.h>

#define BATCH   8
#define SEQ     1024
#define DIM     768
#define HEADS   12
#define DHEAD   64
#define INNER   768
#define NQKV    2304
#define MROWS   8192
#define SC_LOG2E 0.1803368801111244f

// ---------------------------------------------------------------------------
// Persistent fp16 scratch.
// Split (hi+lo, ~22-bit): Q (S-side A), V (PV-side B).
// Single fp16 (2^-12): X, W_qkv, K, W_out, AO.  (6 single sides -> ~5.7e-4)
// ---------------------------------------------------------------------------
__device__ __half g_Xs [MROWS*DIM];
__device__ __half g_WQs[DIM*NQKV];
__device__ __half g_WOs[INNER*DIM];
__device__ __half g_Qhi[BATCH*HEADS*SEQ*DHEAD], g_Qlo[BATCH*HEADS*SEQ*DHEAD];
__device__ __half g_Ks [BATCH*HEADS*SEQ*DHEAD];
__device__ __half g_Vhi[BATCH*HEADS*SEQ*DHEAD], g_Vlo[BATCH*HEADS*SEQ*DHEAD];
__device__ __half g_AOs[MROWS*INNER];

// ---------------------------------------------------------------------------
// Helpers
// ---------------------------------------------------------------------------
__device__ __forceinline__ uint32_t smem_u32(const void* p) {
    uint32_t a;
    asm("{ .reg .u64 t; cvta.to.shared.u64 t, %1; cvt.u32.u64 %0, t; }" : "=r"(a) : "l"(p));
    return a;
}
__device__ __forceinline__ void ldsm4(uint32_t addr, uint32_t* r) {
    asm volatile("ldmatrix.sync.aligned.m8n8.x4.shared.b16 {%0,%1,%2,%3}, [%4];"
                 : "=r"(r[0]), "=r"(r[1]), "=r"(r[2]), "=r"(r[3]) : "r"(addr));
}
__device__ __forceinline__ void ldsm4t(uint32_t addr, uint32_t* r) {
    asm volatile("ldmatrix.sync.aligned.m8n8.x4.trans.shared.b16 {%0,%1,%2,%3}, [%4];"
                 : "=r"(r[0]), "=r"(r[1]), "=r"(r[2]), "=r"(r[3]) : "r"(addr));
}
__device__ __forceinline__ void mma16816(float* c, const uint32_t* a, uint32_t b0, uint32_t b1) {
    asm volatile("mma.sync.aligned.m16n8k16.row.col.f32.f16.f16.f32 "
                 "{%0,%1,%2,%3}, {%4,%5,%6,%7}, {%8,%9}, {%0,%1,%2,%3};"
                 : "+f"(c[0]), "+f"(c[1]), "+f"(c[2]), "+f"(c[3])
                 : "r"(a[0]), "r"(a[1]), "r"(a[2]), "r"(a[3]), "r"(b0), "r"(b1));
}
__device__ __forceinline__ float fast_exp2(float x) {
    float y;
    asm("ex2.approx.f32 %0, %1;" : "=f"(y) : "f"(x));
    return y;
}
__device__ __forceinline__ void cpa16(uint32_t dst, const void* src) {
    asm volatile("cp.async.cg.shared.global [%0], [%1], 16;" :: "r"(dst), "l"(src));
}
#define CP_COMMIT() asm volatile("cp.async.commit_group;" ::: "memory")

__device__ __forceinline__ void split_pack_h(float x, float y, __half2& h2, __half2& l2) {
    __half hx = __float2half_rn(x);
    __half hy = __float2half_rn(y);
    h2 = __halves2half2(hx, hy);
    l2 = __halves2half2(__float2half_rn(x - __half2float(hx)),
                        __float2half_rn(y - __half2float(hy)));
}
__device__ __forceinline__ uint32_t pack_h2(float x, float y) {
    __half2 h = __halves2half2(__float2half_rn(x), __float2half_rn(y));
    return *reinterpret_cast<uint32_t*>(&h);
}

// ---------------------------------------------------------------------------
// Pre-convert fp32 -> single fp16. SEL 0: X, 1: Wqkv, 2: Wout.
// ---------------------------------------------------------------------------
template<int SEL>
__global__ void cvt_h(const float* __restrict__ src, int n)
{
    __half* dst = (SEL == 0) ? g_Xs : (SEL == 1) ? g_WQs : g_WOs;
    const int i = (blockIdx.x * blockDim.x + threadIdx.x) * 4;
    if (i >= n) return;
    float4 v = *(const float4*)(src + i);
    *(__half2*)(dst + i)     = __halves2half2(__float2half_rn(v.x), __float2half_rn(v.y));
    *(__half2*)(dst + i + 2) = __halves2half2(__float2half_rn(v.z), __float2half_rn(v.w));
}

// ---------------------------------------------------------------------------
// GEMM: single-pass fp16 (A single, B single), K-chunk 64, double-buffered,
// 2 CTAs/SM. A stage rows 144B, B stage rows 272B.
// MODE 0: X @ Wqkv -> scatter Q(split,scaled)/K(single)/V(split)
// MODE 1: AO @ Wout + bias -> fp32 out
// ---------------------------------------------------------------------------
#define G_A   0
#define G_B   18432
#define G_STAGE 35840
#define G_SMEM_BYTES (2*G_STAGE)   // 71680

template<int MODE>
__global__ void __launch_bounds__(256, 2)
gemm_tc(const float* __restrict__ bias, float* __restrict__ out)
{
    extern __shared__ char smem[];
    const uint32_t sb = smem_u32(smem);
    const int tid  = threadIdx.x;
    const int lane = tid & 31;
    const int wid  = tid >> 5;
    const int wm   = wid & 3;
    const int wn   = wid >> 2;
    const int bx = blockIdx.x, by = blockIdx.y;

    const __half* As = (MODE == 0) ? g_Xs  : g_AOs;
    const __half* Bs = (MODE == 0) ? g_WQs : g_WOs;
    const int ldb = (MODE == 0) ? NQKV : DIM;

    float acc[2][8][4];
    #pragma unroll
    for (int i = 0; i < 2; i++)
        #pragma unroll
        for (int j = 0; j < 8; j++)
            #pragma unroll
            for (int k = 0; k < 4; k++) acc[i][j][k] = 0.f;

    const int lrow = lane & 15;
    const int lc16 = (lane >> 4) * 16;
    const uint32_t aA = sb + G_A + (uint32_t)((wm*32 + lrow)*144) + lc16;
    const uint32_t aB = sb + G_B + (uint32_t)(lrow*272) + (uint32_t)(wn*128) + lc16;

    auto prefetch = [&](int ch, int st) {
        const int k0 = ch * 64;
        const uint32_t sa = sb + (uint32_t)st * G_STAGE;
        #pragma unroll
        for (int i = tid; i < 1024; i += 256) {
            const int row = i >> 3, seg = i & 7;
            cpa16(sa + G_A + row*144 + seg*16,
                  As + (size_t)(by*128 + row)*768 + k0 + seg*8);
        }
        #pragma unroll
        for (int i = tid; i < 1024; i += 256) {
            const int row = i >> 4, seg = i & 15;
            cpa16(sa + G_B + row*272 + seg*16,
                  Bs + (size_t)(k0 + row)*ldb + bx*128 + seg*8);
        }
    };

    prefetch(0, 0);
    CP_COMMIT();

    for (int ch = 0; ch < 12; ch++) {
        if (ch + 1 < 12) { prefetch(ch + 1, (ch + 1) & 1); CP_COMMIT(); }
        if (ch + 1 < 12) { asm volatile("cp.async.wait_group 1;" ::: "memory"); }
        else             { asm volatile("cp.async.wait_group 0;" ::: "memory"); }
        __syncthreads();

        const uint32_t so = (uint32_t)(ch & 1) * G_STAGE;
        #pragma unroll
        for (int ks = 0; ks < 4; ks++) {
            uint32_t ah[2][4];
            ldsm4(aA + so + ks*32,          ah[0]);
            ldsm4(aA + so + 16*144 + ks*32, ah[1]);
            uint32_t bh[4][4];
            #pragma unroll
            for (int np = 0; np < 4; np++)
                ldsm4t(aB + so + ks*4352 + np*32, bh[np]);
            #pragma unroll
            for (int np = 0; np < 4; np++)
                #pragma unroll
                for (int mt = 0; mt < 2; mt++) {
                    mma16816(acc[mt][np*2+0], ah[mt], bh[np][0], bh[np][1]);
                    mma16816(acc[mt][np*2+1], ah[mt], bh[np][2], bh[np][3]);
                }
        }
        __syncthreads();
    }

    // Epilogue
    #pragma unroll
    for (int mt = 0; mt < 2; mt++) {
        const int row0 = by*128 + wm*32 + mt*16 + (lane >> 2);
        #pragma unroll
        for (int nt = 0; nt < 8; nt++) {
            const int col = bx*128 + wn*64 + nt*8 + (lane & 3)*2;
            if (MODE == 0) {
                const int sel = col / INNER;
                const int cr = col - sel*INNER;
                const int h = cr >> 6, d = cr & 63;
                #pragma unroll
                for (int rr = 0; rr < 2; rr++) {
                    const int r = row0 + rr*8;
                    const int b = r >> 10, nn = r & 1023;
                    const size_t idx = (size_t)(((b*HEADS + h) << 10) + nn)*DHEAD + d;
                    const float v0 = acc[mt][nt][rr*2+0];
                    const float v1 = acc[mt][nt][rr*2+1];
                    if (sel == 1) {
                        *(__half2*)(g_Ks + idx) =
                            __halves2half2(__float2half_rn(v0), __float2half_rn(v1));
                    } else {
                        const float sc = (sel == 0) ? SC_LOG2E : 1.f;
                        __half* dhi = (sel == 0) ? g_Qhi : g_Vhi;
                        __half* dlo = (sel == 0) ? g_Qlo : g_Vlo;
                        __half2 h2, l2;
                        split_pack_h(v0*sc, v1*sc, h2, l2);
                        *(__half2*)(dhi + idx) = h2;
                        *(__half2*)(dlo + idx) = l2;
                    }
                }
            } else {
                const float b0 = bias[col], b1 = bias[col+1];
                *(float2*)&out[(size_t)row0*DIM + col] =
                    make_float2(acc[mt][nt][0] + b0, acc[mt][nt][1] + b1);
                *(float2*)&out[(size_t)(row0+8)*DIM + col] =
                    make_float2(acc[mt][nt][2] + b0, acc[mt][nt][3] + b1);
            }
        }
    }
}

// ---------------------------------------------------------------------------
// Attention, P-in-registers (unchanged numerics from R10), AO single store.
// 8 warps x 16 q rows; warp covers all 64 keys and all 64 d.
// ---------------------------------------------------------------------------
#define A_QHI 0
#define A_QLO 18432
#define A_KV0 36864
#define A_KSo  0
#define A_VHIo 9216
#define A_VLOo 18432
#define A_KVSTAGE 27648
#define A_SMEM_BYTES (36864 + 2*27648)   // 92160

__global__ void __launch_bounds__(256, 2)
attn_tc()
{
    extern __shared__ char smem[];
    const uint32_t sb = smem_u32(smem);
    const int tid  = threadIdx.x;
    const int lane = tid & 31;
    const int wid  = tid >> 5;
    const int bh = blockIdx.y;
    const int q0 = blockIdx.x * 128;

    const size_t base = (size_t)bh * SEQ * DHEAD;

    auto prefetchKV = [&](int c, int st) {
        const size_t g0 = base + (size_t)c*64*DHEAD;
        const uint32_t sa = sb + A_KV0 + (uint32_t)st * A_KVSTAGE;
        #pragma unroll
        for (int i = tid; i < 512; i += 256) {
            const int row = i >> 3, seg = i & 7;
            const uint32_t d = sa + row*144 + seg*16;
            const size_t g = g0 + row*64 + seg*8;
            cpa16(d + A_KSo,  g_Ks  + g);
            cpa16(d + A_VHIo, g_Vhi + g);
            cpa16(d + A_VLOo, g_Vlo + g);
        }
    };

    #pragma unroll
    for (int i = tid; i < 1024; i += 256) {
        const int row = i >> 3, seg = i & 7;
        const uint32_t d = sb + A_QHI + row*144 + seg*16;
        const size_t g = base + (size_t)(q0 + row)*DHEAD + seg*8;
        cpa16(d,                 g_Qhi + g);
        cpa16(d + (A_QLO-A_QHI), g_Qlo + g);
    }
    prefetchKV(0, 0);
    CP_COMMIT();

    float o[8][4];
    #pragma unroll
    for (int j = 0; j < 8; j++)
        #pragma unroll
        for (int k = 0; k < 4; k++) o[j][k] = 0.f;
    float rs0 = 0.f, rs1 = 0.f;

    const int lrow = lane & 15;
    const int lc16 = (lane >> 4) * 16;
    const uint32_t aQ = sb + A_QHI + (uint32_t)((wid*16 + lrow)*144) + lc16;
    const uint32_t aK = sb + A_KV0 + A_KSo  + (uint32_t)(lrow*144) + lc16;
    const uint32_t aV = sb + A_KV0 + A_VHIo + (uint32_t)(lrow*144) + lc16;

    for (int c = 0; c < 16; c++) {
        if (c + 1 < 16) { prefetchKV(c + 1, (c + 1) & 1); CP_COMMIT(); }
        if (c + 1 < 16) { asm volatile("cp.async.wait_group 1;" ::: "memory"); }
        else            { asm volatile("cp.async.wait_group 0;" ::: "memory"); }
        __syncthreads();

        const uint32_t so = (uint32_t)(c & 1) * A_KVSTAGE;

        // ---- S = Q @ K^T: 2 passes (Qhi, Qlo), K single ----
        float s[8][4];
        #pragma unroll
        for (int j = 0; j < 8; j++)
            #pragma unroll
            for (int k = 0; k < 4; k++) s[j][k] = 0.f;

        #pragma unroll
        for (int ks = 0; ks < 4; ks++) {
            uint32_t qh[4], ql[4];
            ldsm4(aQ + ks*32,                 qh);
            ldsm4(aQ + (A_QLO-A_QHI) + ks*32, ql);
            uint32_t kh[4][4];
            #pragma unroll
            for (int np = 0; np < 4; np++)
                ldsm4(aK + so + np*16*144 + ks*32, kh[np]);
            #pragma unroll
            for (int np = 0; np < 4; np++) {
                mma16816(s[np*2+0], qh, kh[np][0], kh[np][2]);
                mma16816(s[np*2+1], qh, kh[np][1], kh[np][3]);
            }
            #pragma unroll
            for (int np = 0; np < 4; np++) {
                mma16816(s[np*2+0], ql, kh[np][0], kh[np][2]);
                mma16816(s[np*2+1], ql, kh[np][1], kh[np][3]);
            }
        }

        // ---- P = 2^S in registers -> fp16 A-fragments ----
        uint32_t pa[4][4];
        #pragma unroll
        for (int kf = 0; kf < 4; kf++) {
            const int t0 = 2*kf, t1 = 2*kf + 1;
            const float e0 = fast_exp2(s[t0][0]);
            const float e1 = fast_exp2(s[t0][1]);
            const float e2 = fast_exp2(s[t0][2]);
            const float e3 = fast_exp2(s[t0][3]);
            const float f0 = fast_exp2(s[t1][0]);
            const float f1 = fast_exp2(s[t1][1]);
            const float f2 = fast_exp2(s[t1][2]);
            const float f3 = fast_exp2(s[t1][3]);
            rs0 += e0 + e1 + f0 + f1;
            rs1 += e2 + e3 + f2 + f3;
            pa[kf][0] = pack_h2(e0, e1);
            pa[kf][1] = pack_h2(e2, e3);
            pa[kf][2] = pack_h2(f0, f1);
            pa[kf][3] = pack_h2(f2, f3);
        }

        // ---- O += P @ V: 2 passes (Vhi, Vlo), P single ----
        #pragma unroll
        for (int kf = 0; kf < 4; kf++) {
            uint32_t vh[4][4], vl[4][4];
            #pragma unroll
            for (int np = 0; np < 4; np++) {
                ldsm4t(aV + so + kf*16*144 + np*32,                   vh[np]);
                ldsm4t(aV + so + (A_VLOo-A_VHIo) + kf*16*144 + np*32, vl[np]);
            }
            #pragma unroll
            for (int np = 0; np < 4; np++) {
                mma16816(o[np*2+0], pa[kf], vh[np][0], vh[np][1]);
                mma16816(o[np*2+1], pa[kf], vh[np][2], vh[np][3]);
            }
            #pragma unroll
            for (int np = 0; np < 4; np++) {
                mma16816(o[np*2+0], pa[kf], vl[np][0], vl[np][1]);
                mma16816(o[np*2+1], pa[kf], vl[np][2], vl[np][3]);
            }
        }
        __syncthreads();
    }

    rs0 += __shfl_xor_sync(0xffffffffu, rs0, 1);
    rs0 += __shfl_xor_sync(0xffffffffu, rs0, 2);
    rs1 += __shfl_xor_sync(0xffffffffu, rs1, 1);
    rs1 += __shfl_xor_sync(0xffffffffu, rs1, 2);
    const float inv0 = 1.f / rs0;
    const float inv1 = 1.f / rs1;

    // Normalize + single fp16 AO store
    const int b = bh / HEADS;
    const int h = bh - b*HEADS;
    const int row0 = q0 + wid*16 + (lane >> 2);
    #pragma unroll
    for (int nt = 0; nt < 8; nt++) {
        const int d = nt*8 + (lane & 3)*2;
        const size_t i0 = (size_t)(b*SEQ + row0)*INNER + h*DHEAD + d;
        const size_t i1 = (size_t)(b*SEQ + row0 + 8)*INNER + h*DHEAD + d;
        *(__half2*)(g_AOs + i0) =
            __halves2half2(__float2half_rn(o[nt][0]*inv0), __float2half_rn(o[nt][1]*inv0));
        *(__half2*)(g_AOs + i1) =
            __halves2half2(__float2half_rn(o[nt][2]*inv1), __float2half_rn(o[nt][3]*inv1));
    }
}

// ---------------------------------------------------------------------------
// Launch
// ---------------------------------------------------------------------------
extern "C" void kernel_launch(void* const* d_in, const int* in_sizes, int n_in,
                              void* d_out, int out_size)
{
    const float* x     = (const float*)d_in[0];
    const float* w_qkv = (const float*)d_in[1];
    const float* w_out = (const float*)d_in[2];
    const float* b_out = (const float*)d_in[3];
    float* out = (float*)d_out;

    cudaFuncSetAttribute(gemm_tc<0>, cudaFuncAttributeMaxDynamicSharedMemorySize, G_SMEM_BYTES);
    cudaFuncSetAttribute(gemm_tc<1>, cudaFuncAttributeMaxDynamicSharedMemorySize, G_SMEM_BYTES);
    cudaFuncSetAttribute(attn_tc,    cudaFuncAttributeMaxDynamicSharedMemorySize, A_SMEM_BYTES);

    cvt_h<0><<<(MROWS*DIM)/1024, 256>>>(x, MROWS*DIM);
    cvt_h<1><<<(DIM*NQKV)/1024, 256>>>(w_qkv, DIM*NQKV);
    cvt_h<2><<<(INNER*DIM)/1024, 256>>>(w_out, INNER*DIM);

    dim3 g1(NQKV/128, MROWS/128);   // 18 x 64
    gemm_tc<0><<<g1, 256, G_SMEM_BYTES>>>(nullptr, nullptr);

    dim3 g2(SEQ/128, BATCH*HEADS);  // 8 x 96
    attn_tc<<<g2, 256, A_SMEM_BYTES>>>();

    dim3 g3(DIM/128, MROWS/128);    // 6 x 64
    gemm_tc<1><<<g3, 256, G_SMEM_BYTES>>>(b_out, out);
}

// round 12
// speedup vs baseline: 2.8429x; 1.2904x over previous
#include <cuda_runtime.h>
#include <cuda_fp16.h>
#include <cstdint>
#include <math.h>

#define BATCH   8
#define SEQ     1024
#define DIM     768
#define HEADS   12
#define DHEAD   64
#define INNER   768
#define NQKV    2304
#define MROWS   8192
#define SC_LOG2E 0.1803368801111244f

// ---------------------------------------------------------------------------
// Persistent fp16 scratch — ALL single fp16 now (8 single matmul sides,
// calibrated error model: sqrt(8) * 2.34e-4 * 1.04 ~= 6.9e-4 < 1e-3).
// ---------------------------------------------------------------------------
__device__ __half g_Xs [MROWS*DIM];
__device__ __half g_WQs[DIM*NQKV];
__device__ __half g_WOs[INNER*DIM];
__device__ __half g_Qs [BATCH*HEADS*SEQ*DHEAD];
__device__ __half g_Ks [BATCH*HEADS*SEQ*DHEAD];
__device__ __half g_Vs [BATCH*HEADS*SEQ*DHEAD];
__device__ __half g_AOs[MROWS*INNER];

// ---------------------------------------------------------------------------
// Helpers
// ---------------------------------------------------------------------------
__device__ __forceinline__ uint32_t smem_u32(const void* p) {
    uint32_t a;
    asm("{ .reg .u64 t; cvta.to.shared.u64 t, %1; cvt.u32.u64 %0, t; }" : "=r"(a) : "l"(p));
    return a;
}
__device__ __forceinline__ void ldsm4(uint32_t addr, uint32_t* r) {
    asm volatile("ldmatrix.sync.aligned.m8n8.x4.shared.b16 {%0,%1,%2,%3}, [%4];"
                 : "=r"(r[0]), "=r"(r[1]), "=r"(r[2]), "=r"(r[3]) : "r"(addr));
}
__device__ __forceinline__ void ldsm4t(uint32_t addr, uint32_t* r) {
    asm volatile("ldmatrix.sync.aligned.m8n8.x4.trans.shared.b16 {%0,%1,%2,%3}, [%4];"
                 : "=r"(r[0]), "=r"(r[1]), "=r"(r[2]), "=r"(r[3]) : "r"(addr));
}
__device__ __forceinline__ void mma16816(float* c, const uint32_t* a, uint32_t b0, uint32_t b1) {
    asm volatile("mma.sync.aligned.m16n8k16.row.col.f32.f16.f16.f32 "
                 "{%0,%1,%2,%3}, {%4,%5,%6,%7}, {%8,%9}, {%0,%1,%2,%3};"
                 : "+f"(c[0]), "+f"(c[1]), "+f"(c[2]), "+f"(c[3])
                 : "r"(a[0]), "r"(a[1]), "r"(a[2]), "r"(a[3]), "r"(b0), "r"(b1));
}
__device__ __forceinline__ float fast_exp2(float x) {
    float y;
    asm("ex2.approx.f32 %0, %1;" : "=f"(y) : "f"(x));
    return y;
}
__device__ __forceinline__ void cpa16(uint32_t dst, const void* src) {
    asm volatile("cp.async.cg.shared.global [%0], [%1], 16;" :: "r"(dst), "l"(src));
}
#define CP_COMMIT() asm volatile("cp.async.commit_group;" ::: "memory")

__device__ __forceinline__ uint32_t pack_h2(float x, float y) {
    __half2 h = __halves2half2(__float2half_rn(x), __float2half_rn(y));
    return *reinterpret_cast<uint32_t*>(&h);
}

// ---------------------------------------------------------------------------
// Pre-convert fp32 -> fp16. SEL 0: X, 1: Wqkv, 2: Wout.
// ---------------------------------------------------------------------------
template<int SEL>
__global__ void cvt_h(const float* __restrict__ src, int n)
{
    __half* dst = (SEL == 0) ? g_Xs : (SEL == 1) ? g_WQs : g_WOs;
    const int i = (blockIdx.x * blockDim.x + threadIdx.x) * 4;
    if (i >= n) return;
    float4 v = *(const float4*)(src + i);
    *(__half2*)(dst + i)     = __halves2half2(__float2half_rn(v.x), __float2half_rn(v.y));
    *(__half2*)(dst + i + 2) = __halves2half2(__float2half_rn(v.z), __float2half_rn(v.w));
}

// ---------------------------------------------------------------------------
// GEMM: single-pass fp16, K-chunk 64, double-buffered, 2 CTAs/SM.
// MODE 0: X @ Wqkv -> scatter Q(scaled)/K/V single fp16
// MODE 1: AO @ Wout + bias -> fp32 out
// ---------------------------------------------------------------------------
#define G_A   0
#define G_B   18432
#define G_STAGE 35840
#define G_SMEM_BYTES (2*G_STAGE)   // 71680

template<int MODE>
__global__ void __launch_bounds__(256, 2)
gemm_tc(const float* __restrict__ bias, float* __restrict__ out)
{
    extern __shared__ char smem[];
    const uint32_t sb = smem_u32(smem);
    const int tid  = threadIdx.x;
    const int lane = tid & 31;
    const int wid  = tid >> 5;
    const int wm   = wid & 3;
    const int wn   = wid >> 2;
    const int bx = blockIdx.x, by = blockIdx.y;

    const __half* As = (MODE == 0) ? g_Xs  : g_AOs;
    const __half* Bs = (MODE == 0) ? g_WQs : g_WOs;
    const int ldb = (MODE == 0) ? NQKV : DIM;

    float acc[2][8][4];
    #pragma unroll
    for (int i = 0; i < 2; i++)
        #pragma unroll
        for (int j = 0; j < 8; j++)
            #pragma unroll
            for (int k = 0; k < 4; k++) acc[i][j][k] = 0.f;

    const int lrow = lane & 15;
    const int lc16 = (lane >> 4) * 16;
    const uint32_t aA = sb + G_A + (uint32_t)((wm*32 + lrow)*144) + lc16;
    const uint32_t aB = sb + G_B + (uint32_t)(lrow*272) + (uint32_t)(wn*128) + lc16;

    auto prefetch = [&](int ch, int st) {
        const int k0 = ch * 64;
        const uint32_t sa = sb + (uint32_t)st * G_STAGE;
        #pragma unroll
        for (int i = tid; i < 1024; i += 256) {
            const int row = i >> 3, seg = i & 7;
            cpa16(sa + G_A + row*144 + seg*16,
                  As + (size_t)(by*128 + row)*768 + k0 + seg*8);
        }
        #pragma unroll
        for (int i = tid; i < 1024; i += 256) {
            const int row = i >> 4, seg = i & 15;
            cpa16(sa + G_B + row*272 + seg*16,
                  Bs + (size_t)(k0 + row)*ldb + bx*128 + seg*8);
        }
    };

    prefetch(0, 0);
    CP_COMMIT();

    for (int ch = 0; ch < 12; ch++) {
        if (ch + 1 < 12) { prefetch(ch + 1, (ch + 1) & 1); CP_COMMIT(); }
        if (ch + 1 < 12) { asm volatile("cp.async.wait_group 1;" ::: "memory"); }
        else             { asm volatile("cp.async.wait_group 0;" ::: "memory"); }
        __syncthreads();

        const uint32_t so = (uint32_t)(ch & 1) * G_STAGE;
        #pragma unroll
        for (int ks = 0; ks < 4; ks++) {
            uint32_t ah[2][4];
            ldsm4(aA + so + ks*32,          ah[0]);
            ldsm4(aA + so + 16*144 + ks*32, ah[1]);
            uint32_t bh[4][4];
            #pragma unroll
            for (int np = 0; np < 4; np++)
                ldsm4t(aB + so + ks*4352 + np*32, bh[np]);
            #pragma unroll
            for (int np = 0; np < 4; np++)
                #pragma unroll
                for (int mt = 0; mt < 2; mt++) {
                    mma16816(acc[mt][np*2+0], ah[mt], bh[np][0], bh[np][1]);
                    mma16816(acc[mt][np*2+1], ah[mt], bh[np][2], bh[np][3]);
                }
        }
        __syncthreads();
    }

    // Epilogue
    #pragma unroll
    for (int mt = 0; mt < 2; mt++) {
        const int row0 = by*128 + wm*32 + mt*16 + (lane >> 2);
        #pragma unroll
        for (int nt = 0; nt < 8; nt++) {
            const int col = bx*128 + wn*64 + nt*8 + (lane & 3)*2;
            if (MODE == 0) {
                const int sel = col / INNER;
                const int cr = col - sel*INNER;
                const int h = cr >> 6, d = cr & 63;
                __half* dst = (sel == 0) ? g_Qs : (sel == 1) ? g_Ks : g_Vs;
                const float sc = (sel == 0) ? SC_LOG2E : 1.f;
                #pragma unroll
                for (int rr = 0; rr < 2; rr++) {
                    const int r = row0 + rr*8;
                    const int b = r >> 10, nn = r & 1023;
                    const size_t idx = (size_t)(((b*HEADS + h) << 10) + nn)*DHEAD + d;
                    *(__half2*)(dst + idx) =
                        __halves2half2(__float2half_rn(acc[mt][nt][rr*2+0]*sc),
                                       __float2half_rn(acc[mt][nt][rr*2+1]*sc));
                }
            } else {
                const float b0 = bias[col], b1 = bias[col+1];
                *(float2*)&out[(size_t)row0*DIM + col] =
                    make_float2(acc[mt][nt][0] + b0, acc[mt][nt][1] + b1);
                *(float2*)&out[(size_t)(row0+8)*DIM + col] =
                    make_float2(acc[mt][nt][2] + b0, acc[mt][nt][3] + b1);
            }
        }
    }
}

// ---------------------------------------------------------------------------
// Attention, single-pass everywhere, P-in-registers.
// 8 warps x 16 q rows; warp covers all 64 keys and all 64 d.
// KV double-buffered, 2 CTAs/SM, 2 syncs/chunk.
// ---------------------------------------------------------------------------
#define A_Q   0
#define A_KV0 18432
#define A_KSo 0
#define A_VSo 9216
#define A_KVSTAGE 18432
#define A_SMEM_BYTES (18432 + 2*18432)   // 55296

__global__ void __launch_bounds__(256, 2)
attn_tc()
{
    extern __shared__ char smem[];
    const uint32_t sb = smem_u32(smem);
    const int tid  = threadIdx.x;
    const int lane = tid & 31;
    const int wid  = tid >> 5;
    const int bh = blockIdx.y;
    const int q0 = blockIdx.x * 128;

    const size_t base = (size_t)bh * SEQ * DHEAD;

    auto prefetchKV = [&](int c, int st) {
        const size_t g0 = base + (size_t)c*64*DHEAD;
        const uint32_t sa = sb + A_KV0 + (uint32_t)st * A_KVSTAGE;
        #pragma unroll
        for (int i = tid; i < 512; i += 256) {
            const int row = i >> 3, seg = i & 7;
            const uint32_t d = sa + row*144 + seg*16;
            const size_t g = g0 + row*64 + seg*8;
            cpa16(d + A_KSo, g_Ks + g);
            cpa16(d + A_VSo, g_Vs + g);
        }
    };

    // Q (single) + first K/V chunk
    #pragma unroll
    for (int i = tid; i < 1024; i += 256) {
        const int row = i >> 3, seg = i & 7;
        cpa16(sb + A_Q + row*144 + seg*16,
              g_Qs + base + (size_t)(q0 + row)*DHEAD + seg*8);
    }
    prefetchKV(0, 0);
    CP_COMMIT();

    float o[8][4];
    #pragma unroll
    for (int j = 0; j < 8; j++)
        #pragma unroll
        for (int k = 0; k < 4; k++) o[j][k] = 0.f;
    float rs0 = 0.f, rs1 = 0.f;

    const int lrow = lane & 15;
    const int lc16 = (lane >> 4) * 16;
    const uint32_t aQ = sb + A_Q   + (uint32_t)((wid*16 + lrow)*144) + lc16;
    const uint32_t aK = sb + A_KV0 + A_KSo + (uint32_t)(lrow*144) + lc16;
    const uint32_t aV = sb + A_KV0 + A_VSo + (uint32_t)(lrow*144) + lc16;

    for (int c = 0; c < 16; c++) {
        if (c + 1 < 16) { prefetchKV(c + 1, (c + 1) & 1); CP_COMMIT(); }
        if (c + 1 < 16) { asm volatile("cp.async.wait_group 1;" ::: "memory"); }
        else            { asm volatile("cp.async.wait_group 0;" ::: "memory"); }
        __syncthreads();

        const uint32_t so = (uint32_t)(c & 1) * A_KVSTAGE;

        // ---- S = Q @ K^T (single pass) ----
        float s[8][4];
        #pragma unroll
        for (int j = 0; j < 8; j++)
            #pragma unroll
            for (int k = 0; k < 4; k++) s[j][k] = 0.f;

        #pragma unroll
        for (int ks = 0; ks < 4; ks++) {
            uint32_t qh[4];
            ldsm4(aQ + ks*32, qh);
            uint32_t kh[4][4];
            #pragma unroll
            for (int np = 0; np < 4; np++)
                ldsm4(aK + so + np*16*144 + ks*32, kh[np]);
            // non-trans pairing: {r0,r2} / {r1,r3}
            #pragma unroll
            for (int np = 0; np < 4; np++) {
                mma16816(s[np*2+0], qh, kh[np][0], kh[np][2]);
                mma16816(s[np*2+1], qh, kh[np][1], kh[np][3]);
            }
        }

        // ---- P = 2^S in registers -> fp16 A-fragments ----
        uint32_t pa[4][4];
        #pragma unroll
        for (int kf = 0; kf < 4; kf++) {
            const int t0 = 2*kf, t1 = 2*kf + 1;
            const float e0 = fast_exp2(s[t0][0]);
            const float e1 = fast_exp2(s[t0][1]);
            const float e2 = fast_exp2(s[t0][2]);
            const float e3 = fast_exp2(s[t0][3]);
            const float f0 = fast_exp2(s[t1][0]);
            const float f1 = fast_exp2(s[t1][1]);
            const float f2 = fast_exp2(s[t1][2]);
            const float f3 = fast_exp2(s[t1][3]);
            rs0 += e0 + e1 + f0 + f1;
            rs1 += e2 + e3 + f2 + f3;
            pa[kf][0] = pack_h2(e0, e1);
            pa[kf][1] = pack_h2(e2, e3);
            pa[kf][2] = pack_h2(f0, f1);
            pa[kf][3] = pack_h2(f2, f3);
        }

        // ---- O += P @ V (single pass) ----
        #pragma unroll
        for (int kf = 0; kf < 4; kf++) {
            uint32_t vh[4][4];
            #pragma unroll
            for (int np = 0; np < 4; np++)
                ldsm4t(aV + so + kf*16*144 + np*32, vh[np]);
            // trans pairing: {r0,r1} / {r2,r3}
            #pragma unroll
            for (int np = 0; np < 4; np++) {
                mma16816(o[np*2+0], pa[kf], vh[np][0], vh[np][1]);
                mma16816(o[np*2+1], pa[kf], vh[np][2], vh[np][3]);
            }
        }
        __syncthreads();   // stage reads done before next prefetch overwrites
    }

    rs0 += __shfl_xor_sync(0xffffffffu, rs0, 1);
    rs0 += __shfl_xor_sync(0xffffffffu, rs0, 2);
    rs1 += __shfl_xor_sync(0xffffffffu, rs1, 1);
    rs1 += __shfl_xor_sync(0xffffffffu, rs1, 2);
    const float inv0 = 1.f / rs0;
    const float inv1 = 1.f / rs1;

    // Normalize + single fp16 AO store
    const int b = bh / HEADS;
    const int h = bh - b*HEADS;
    const int row0 = q0 + wid*16 + (lane >> 2);
    #pragma unroll
    for (int nt = 0; nt < 8; nt++) {
        const int d = nt*8 + (lane & 3)*2;
        const size_t i0 = (size_t)(b*SEQ + row0)*INNER + h*DHEAD + d;
        const size_t i1 = (size_t)(b*SEQ + row0 + 8)*INNER + h*DHEAD + d;
        *(__half2*)(g_AOs + i0) =
            __halves2half2(__float2half_rn(o[nt][0]*inv0), __float2half_rn(o[nt][1]*inv0));
        *(__half2*)(g_AOs + i1) =
            __halves2half2(__float2half_rn(o[nt][2]*inv1), __float2half_rn(o[nt][3]*inv1));
    }
}

// ---------------------------------------------------------------------------
// Launch
// ---------------------------------------------------------------------------
extern "C" void kernel_launch(void* const* d_in, const int* in_sizes, int n_in,
                              void* d_out, int out_size)
{
    const float* x     = (const float*)d_in[0];
    const float* w_qkv = (const float*)d_in[1];
    const float* w_out = (const float*)d_in[2];
    const float* b_out = (const float*)d_in[3];
    float* out = (float*)d_out;

    cudaFuncSetAttribute(gemm_tc<0>, cudaFuncAttributeMaxDynamicSharedMemorySize, G_SMEM_BYTES);
    cudaFuncSetAttribute(gemm_tc<1>, cudaFuncAttributeMaxDynamicSharedMemorySize, G_SMEM_BYTES);
    cudaFuncSetAttribute(attn_tc,    cudaFuncAttributeMaxDynamicSharedMemorySize, A_SMEM_BYTES);

    cvt_h<0><<<(MROWS*DIM)/1024, 256>>>(x, MROWS*DIM);
    cvt_h<1><<<(DIM*NQKV)/1024, 256>>>(w_qkv, DIM*NQKV);
    cvt_h<2><<<(INNER*DIM)/1024, 256>>>(w_out, INNER*DIM);

    dim3 g1(NQKV/128, MROWS/128);   // 18 x 64
    gemm_tc<0><<<g1, 256, G_SMEM_BYTES>>>(nullptr, nullptr);

    dim3 g2(SEQ/128, BATCH*HEADS);  // 8 x 96
    attn_tc<<<g2, 256, A_SMEM_BYTES>>>();

    dim3 g3(DIM/128, MROWS/128);    // 6 x 64
    gemm_tc<1><<<g3, 256, G_SMEM_BYTES>>>(b_out, out);
}

// round 14
// speedup vs baseline: 2.9642x; 1.0427x over previous
#include <cuda_runtime.h>
#include <cuda_fp16.h>
#include <cstdint>
#include <math.h>

#define BATCH   8
#define SEQ     1024
#define DIM     768
#define HEADS   12
#define DHEAD   64
#define INNER   768
#define NQKV    2304
#define MROWS   8192
#define SC_LOG2E 0.1803368801111244f
#define ONES_H2 0x3C003C00u   // fp16 1.0 x2

// ---------------------------------------------------------------------------
// Persistent fp16 scratch (all single fp16; error budget fixed at ~6.5e-4)
// ---------------------------------------------------------------------------
__device__ __half g_Xs [MROWS*DIM];
__device__ __half g_WQs[DIM*NQKV];
__device__ __half g_WOs[INNER*DIM];
__device__ __half g_Qs [BATCH*HEADS*SEQ*DHEAD];
__device__ __half g_Ks [BATCH*HEADS*SEQ*DHEAD];
__device__ __half g_Vs [BATCH*HEADS*SEQ*DHEAD];
__device__ __half g_AOs[MROWS*INNER];

// ---------------------------------------------------------------------------
// Helpers
// ---------------------------------------------------------------------------
__device__ __forceinline__ uint32_t smem_u32(const void* p) {
    uint32_t a;
    asm("{ .reg .u64 t; cvta.to.shared.u64 t, %1; cvt.u32.u64 %0, t; }" : "=r"(a) : "l"(p));
    return a;
}
__device__ __forceinline__ void ldsm4(uint32_t addr, uint32_t* r) {
    asm volatile("ldmatrix.sync.aligned.m8n8.x4.shared.b16 {%0,%1,%2,%3}, [%4];"
                 : "=r"(r[0]), "=r"(r[1]), "=r"(r[2]), "=r"(r[3]) : "r"(addr));
}
__device__ __forceinline__ void ldsm4t(uint32_t addr, uint32_t* r) {
    asm volatile("ldmatrix.sync.aligned.m8n8.x4.trans.shared.b16 {%0,%1,%2,%3}, [%4];"
                 : "=r"(r[0]), "=r"(r[1]), "=r"(r[2]), "=r"(r[3]) : "r"(addr));
}
__device__ __forceinline__ void mma16816(float* c, const uint32_t* a, uint32_t b0, uint32_t b1) {
    asm volatile("mma.sync.aligned.m16n8k16.row.col.f32.f16.f16.f32 "
                 "{%0,%1,%2,%3}, {%4,%5,%6,%7}, {%8,%9}, {%0,%1,%2,%3};"
                 : "+f"(c[0]), "+f"(c[1]), "+f"(c[2]), "+f"(c[3])
                 : "r"(a[0]), "r"(a[1]), "r"(a[2]), "r"(a[3]), "r"(b0), "r"(b1));
}
__device__ __forceinline__ float fast_exp2(float x) {
    float y;
    asm("ex2.approx.f32 %0, %1;" : "=f"(y) : "f"(x));
    return y;
}
__device__ __forceinline__ void cpa16(uint32_t dst, const void* src) {
    asm volatile("cp.async.cg.shared.global [%0], [%1], 16;" :: "r"(dst), "l"(src));
}
#define CP_COMMIT() asm volatile("cp.async.commit_group;" ::: "memory")
// Wait so that the group for chunk c is complete, given lookahead 2.
#define CP_WAIT_LA2(c, NC) do { \
    if ((c) + 2 < (NC))      asm volatile("cp.async.wait_group 2;" ::: "memory"); \
    else if ((c) + 1 < (NC)) asm volatile("cp.async.wait_group 1;" ::: "memory"); \
    else                     asm volatile("cp.async.wait_group 0;" ::: "memory"); \
} while (0)

__device__ __forceinline__ uint32_t pack_h2(float x, float y) {
    __half2 h = __halves2half2(__float2half_rn(x), __float2half_rn(y));
    return *reinterpret_cast<uint32_t*>(&h);
}

// ---------------------------------------------------------------------------
// Pre-convert fp32 -> fp16. SEL 0: X, 1: Wqkv, 2: Wout.
// ---------------------------------------------------------------------------
template<int SEL>
__global__ void cvt_h(const float* __restrict__ src, int n)
{
    __half* dst = (SEL == 0) ? g_Xs : (SEL == 1) ? g_WQs : g_WOs;
    const int i = (blockIdx.x * blockDim.x + threadIdx.x) * 4;
    if (i >= n) return;
    float4 v = *(const float4*)(src + i);
    *(__half2*)(dst + i)     = __halves2half2(__float2half_rn(v.x), __float2half_rn(v.y));
    *(__half2*)(dst + i + 2) = __halves2half2(__float2half_rn(v.z), __float2half_rn(v.w));
}

// ---------------------------------------------------------------------------
// GEMM: single-pass fp16, K-chunk 32, 4-stage pipeline / lookahead 2,
// ONE barrier per chunk (prefetch -> wait -> barrier -> compute), 2 CTAs/SM.
// MODE 0: X @ Wqkv -> Q(scaled)/K/V fp16.  MODE 1: AO @ Wout + bias -> fp32.
// ---------------------------------------------------------------------------
#define G_A   0
#define G_B   10240
#define G_STAGE 18944
#define G_SMEM_BYTES (4*G_STAGE)   // 75776
#define G_NCHUNK 24

template<int MODE>
__global__ void __launch_bounds__(256, 2)
gemm_tc(const float* __restrict__ bias, float* __restrict__ out)
{
    extern __shared__ char smem[];
    const uint32_t sb = smem_u32(smem);
    const int tid  = threadIdx.x;
    const int lane = tid & 31;
    const int wid  = tid >> 5;
    const int wm   = wid & 3;
    const int wn   = wid >> 2;
    const int bx = blockIdx.x, by = blockIdx.y;

    const __half* As = (MODE == 0) ? g_Xs  : g_AOs;
    const __half* Bs = (MODE == 0) ? g_WQs : g_WOs;
    const int ldb = (MODE == 0) ? NQKV : DIM;

    float acc[2][8][4];
    #pragma unroll
    for (int i = 0; i < 2; i++)
        #pragma unroll
        for (int j = 0; j < 8; j++)
            #pragma unroll
            for (int k = 0; k < 4; k++) acc[i][j][k] = 0.f;

    const int lrow = lane & 15;
    const int lc16 = (lane >> 4) * 16;
    const uint32_t aA = sb + G_A + (uint32_t)((wm*32 + lrow)*80) + lc16;
    const uint32_t aB = sb + G_B + (uint32_t)(lrow*272) + (uint32_t)(wn*128) + lc16;

    auto prefetch = [&](int ch, int st) {
        const int k0 = ch * 32;
        const uint32_t sa = sb + (uint32_t)st * G_STAGE;
        #pragma unroll
        for (int i = tid; i < 512; i += 256) {
            const int row = i >> 2, seg = i & 3;
            cpa16(sa + G_A + row*80 + seg*16,
                  As + (size_t)(by*128 + row)*768 + k0 + seg*8);
        }
        #pragma unroll
        for (int i = tid; i < 512; i += 256) {
            const int row = i >> 4, seg = i & 15;
            cpa16(sa + G_B + row*272 + seg*16,
                  Bs + (size_t)(k0 + row)*ldb + bx*128 + seg*8);
        }
    };

    prefetch(0, 0); CP_COMMIT();
    prefetch(1, 1); CP_COMMIT();

    for (int ch = 0; ch < G_NCHUNK; ch++) {
        // Writing stage (ch+2)%4 is safe: it was last READ at compute(ch-2),
        // and every warp here has passed barrier(ch-1), which follows compute(ch-2).
        if (ch + 2 < G_NCHUNK) { prefetch(ch + 2, (ch + 2) & 3); CP_COMMIT(); }
        CP_WAIT_LA2(ch, G_NCHUNK);   // this thread's group ch complete
        __syncthreads();             // ALL threads' group-ch copies now visible

        const uint32_t so = (uint32_t)(ch & 3) * G_STAGE;
        #pragma unroll
        for (int ks = 0; ks < 2; ks++) {
            uint32_t ah[2][4];
            ldsm4(aA + so + ks*32,         ah[0]);
            ldsm4(aA + so + 16*80 + ks*32, ah[1]);
            uint32_t bh[4][4];
            #pragma unroll
            for (int np = 0; np < 4; np++)
                ldsm4t(aB + so + ks*4352 + np*32, bh[np]);
            #pragma unroll
            for (int np = 0; np < 4; np++)
                #pragma unroll
                for (int mt = 0; mt < 2; mt++) {
                    mma16816(acc[mt][np*2+0], ah[mt], bh[np][0], bh[np][1]);
                    mma16816(acc[mt][np*2+1], ah[mt], bh[np][2], bh[np][3]);
                }
        }
    }

    // Epilogue
    #pragma unroll
    for (int mt = 0; mt < 2; mt++) {
        const int row0 = by*128 + wm*32 + mt*16 + (lane >> 2);
        #pragma unroll
        for (int nt = 0; nt < 8; nt++) {
            const int col = bx*128 + wn*64 + nt*8 + (lane & 3)*2;
            if (MODE == 0) {
                const int sel = col / INNER;
                const int cr = col - sel*INNER;
                const int h = cr >> 6, d = cr & 63;
                __half* dst = (sel == 0) ? g_Qs : (sel == 1) ? g_Ks : g_Vs;
                const float sc = (sel == 0) ? SC_LOG2E : 1.f;
                #pragma unroll
                for (int rr = 0; rr < 2; rr++) {
                    const int r = row0 + rr*8;
                    const int b = r >> 10, nn = r & 1023;
                    const size_t idx = (size_t)(((b*HEADS + h) << 10) + nn)*DHEAD + d;
                    *(__half2*)(dst + idx) =
                        __halves2half2(__float2half_rn(acc[mt][nt][rr*2+0]*sc),
                                       __float2half_rn(acc[mt][nt][rr*2+1]*sc));
                }
            } else {
                const float b0 = bias[col], b1 = bias[col+1];
                *(float2*)&out[(size_t)row0*DIM + col] =
                    make_float2(acc[mt][nt][0] + b0, acc[mt][nt][1] + b1);
                *(float2*)&out[(size_t)(row0+8)*DIM + col] =
                    make_float2(acc[mt][nt][2] + b0, acc[mt][nt][3] + b1);
            }
        }
    }
}

// ---------------------------------------------------------------------------
// Attention: single-pass, P-in-registers, rowsum via ones-MMA,
// 4-stage KV pipeline / lookahead 2, ONE barrier per chunk, 2 CTAs/SM.
// 8 warps x 16 q rows; warp covers all 64 keys and all 64 d.
// ---------------------------------------------------------------------------
#define A_Q   0
#define A_KV0 18432
#define A_KSo 0
#define A_VSo 9216
#define A_KVSTAGE 18432
#define A_SMEM_BYTES (18432 + 4*A_KVSTAGE)   // 92160
#define A_NCHUNK 16

__global__ void __launch_bounds__(256, 2)
attn_tc()
{
    extern __shared__ char smem[];
    const uint32_t sb = smem_u32(smem);
    const int tid  = threadIdx.x;
    const int lane = tid & 31;
    const int wid  = tid >> 5;
    const int bh = blockIdx.y;
    const int q0 = blockIdx.x * 128;

    const size_t base = (size_t)bh * SEQ * DHEAD;

    auto prefetchKV = [&](int c, int st) {
        const size_t g0 = base + (size_t)c*64*DHEAD;
        const uint32_t sa = sb + A_KV0 + (uint32_t)st * A_KVSTAGE;
        #pragma unroll
        for (int i = tid; i < 512; i += 256) {
            const int row = i >> 3, seg = i & 7;
            const uint32_t d = sa + row*144 + seg*16;
            const size_t g = g0 + row*64 + seg*8;
            cpa16(d + A_KSo, g_Ks + g);
            cpa16(d + A_VSo, g_Vs + g);
        }
    };

    // group 0 = Q + KV chunk 0, group 1 = KV chunk 1
    #pragma unroll
    for (int i = tid; i < 1024; i += 256) {
        const int row = i >> 3, seg = i & 7;
        cpa16(sb + A_Q + row*144 + seg*16,
              g_Qs + base + (size_t)(q0 + row)*DHEAD + seg*8);
    }
    prefetchKV(0, 0); CP_COMMIT();
    prefetchKV(1, 1); CP_COMMIT();

    float o[8][4];
    #pragma unroll
    for (int j = 0; j < 8; j++)
        #pragma unroll
        for (int k = 0; k < 4; k++) o[j][k] = 0.f;
    float rs[4] = {0.f, 0.f, 0.f, 0.f};   // rowsum accumulator (ones-MMA)

    const int lrow = lane & 15;
    const int lc16 = (lane >> 4) * 16;
    const uint32_t aQ = sb + A_Q   + (uint32_t)((wid*16 + lrow)*144) + lc16;
    const uint32_t aK = sb + A_KV0 + A_KSo + (uint32_t)(lrow*144) + lc16;
    const uint32_t aV = sb + A_KV0 + A_VSo + (uint32_t)(lrow*144) + lc16;

    for (int c = 0; c < A_NCHUNK; c++) {
        if (c + 2 < A_NCHUNK) { prefetchKV(c + 2, (c + 2) & 3); CP_COMMIT(); }
        CP_WAIT_LA2(c, A_NCHUNK);
        __syncthreads();             // all threads' group-c copies visible

        const uint32_t so = (uint32_t)(c & 3) * A_KVSTAGE;

        // ---- S = Q @ K^T ----
        float s[8][4];
        #pragma unroll
        for (int j = 0; j < 8; j++)
            #pragma unroll
            for (int k = 0; k < 4; k++) s[j][k] = 0.f;

        #pragma unroll
        for (int ks = 0; ks < 4; ks++) {
            uint32_t qh[4];
            ldsm4(aQ + ks*32, qh);
            uint32_t kh[4][4];
            #pragma unroll
            for (int np = 0; np < 4; np++)
                ldsm4(aK + so + np*16*144 + ks*32, kh[np]);
            // non-trans pairing: {r0,r2} / {r1,r3}
            #pragma unroll
            for (int np = 0; np < 4; np++) {
                mma16816(s[np*2+0], qh, kh[np][0], kh[np][2]);
                mma16816(s[np*2+1], qh, kh[np][1], kh[np][3]);
            }
        }

        // ---- P = 2^S -> fp16 A-fragments; rowsum via ones-MMA ----
        uint32_t pa[4][4];
        #pragma unroll
        for (int kf = 0; kf < 4; kf++) {
            const int t0 = 2*kf, t1 = 2*kf + 1;
            const float e0 = fast_exp2(s[t0][0]);
            const float e1 = fast_exp2(s[t0][1]);
            const float e2 = fast_exp2(s[t0][2]);
            const float e3 = fast_exp2(s[t0][3]);
            const float f0 = fast_exp2(s[t1][0]);
            const float f1 = fast_exp2(s[t1][1]);
            const float f2 = fast_exp2(s[t1][2]);
            const float f3 = fast_exp2(s[t1][3]);
            pa[kf][0] = pack_h2(e0, e1);
            pa[kf][1] = pack_h2(e2, e3);
            pa[kf][2] = pack_h2(f0, f1);
            pa[kf][3] = pack_h2(f2, f3);
            // rowsum from the SAME fp16 P used in PV (exact denominator)
            mma16816(rs, pa[kf], ONES_H2, ONES_H2);
        }

        // ---- O += P @ V ----
        #pragma unroll
        for (int kf = 0; kf < 4; kf++) {
            uint32_t vh[4][4];
            #pragma unroll
            for (int np = 0; np < 4; np++)
                ldsm4t(aV + so + kf*16*144 + np*32, vh[np]);
            // trans pairing: {r0,r1} / {r2,r3}
            #pragma unroll
            for (int np = 0; np < 4; np++) {
                mma16816(o[np*2+0], pa[kf], vh[np][0], vh[np][1]);
                mma16816(o[np*2+1], pa[kf], vh[np][2], vh[np][3]);
            }
        }
    }

    // rs[0] = rowsum(row), rs[2] = rowsum(row+8)
    const float inv0 = 1.f / rs[0];
    const float inv1 = 1.f / rs[2];

    // Normalize + fp16 AO store
    const int b = bh / HEADS;
    const int h = bh - b*HEADS;
    const int row0 = q0 + wid*16 + (lane >> 2);
    #pragma unroll
    for (int nt = 0; nt < 8; nt++) {
        const int d = nt*8 + (lane & 3)*2;
        const size_t i0 = (size_t)(b*SEQ + row0)*INNER + h*DHEAD + d;
        const size_t i1 = (size_t)(b*SEQ + row0 + 8)*INNER + h*DHEAD + d;
        *(__half2*)(g_AOs + i0) =
            __halves2half2(__float2half_rn(o[nt][0]*inv0), __float2half_rn(o[nt][1]*inv0));
        *(__half2*)(g_AOs + i1) =
            __halves2half2(__float2half_rn(o[nt][2]*inv1), __float2half_rn(o[nt][3]*inv1));
    }
}

// ---------------------------------------------------------------------------
// Launch
// ---------------------------------------------------------------------------
extern "C" void kernel_launch(void* const* d_in, const int* in_sizes, int n_in,
                              void* d_out, int out_size)
{
    const float* x     = (const float*)d_in[0];
    const float* w_qkv = (const float*)d_in[1];
    const float* w_out = (const float*)d_in[2];
    const float* b_out = (const float*)d_in[3];
    float* out = (float*)d_out;

    cudaFuncSetAttribute(gemm_tc<0>, cudaFuncAttributeMaxDynamicSharedMemorySize, G_SMEM_BYTES);
    cudaFuncSetAttribute(gemm_tc<1>, cudaFuncAttributeMaxDynamicSharedMemorySize, G_SMEM_BYTES);
    cudaFuncSetAttribute(attn_tc,    cudaFuncAttributeMaxDynamicSharedMemorySize, A_SMEM_BYTES);

    cvt_h<0><<<(MROWS*DIM)/1024, 256>>>(x, MROWS*DIM);
    cvt_h<1><<<(DIM*NQKV)/1024, 256>>>(w_qkv, DIM*NQKV);
    cvt_h<2><<<(INNER*DIM)/1024, 256>>>(w_out, INNER*DIM);

    dim3 g1(NQKV/128, MROWS/128);   // 18 x 64
    gemm_tc<0><<<g1, 256, G_SMEM_BYTES>>>(nullptr, nullptr);

    dim3 g2(SEQ/128, BATCH*HEADS);  // 8 x 96
    attn_tc<<<g2, 256, A_SMEM_BYTES>>>();

    dim3 g3(DIM/128, MROWS/128);    // 6 x 64
    gemm_tc<1><<<g3, 256, G_SMEM_BYTES>>>(b_out, out);
}